// round 7
// baseline (speedup 1.0000x reference)
#include <cuda_runtime.h>
#include <cuda_fp16.h>
#include <cstdint>
#include <math.h>

// ---------------- problem constants ----------------
#define NSENT 4096
#define MKNOW 4096
#define HEADS 8
#define SENTD 1024
#define HD    128

// ---------------- GEMM tile config ----------------
#define BM 128
#define BN 128
#define BKH 32                          // k halves per stage (2 mma k16 steps)
#define TILE_BYTES_H (128 * 64)         // 128 rows x 64B
#define STAGE_BYTES (2 * TILE_BYTES_H)  // A + B = 16 KB
#define STAGES 4
#define SMEM_BYTES (STAGES * STAGE_BYTES)   // 64 KB -> 2 CTAs/SM

// ---------------- scratch (static device arrays) ----------------
__device__ __half g_sent3h[(size_t)NSENT*3*SENTD];
__device__ __half g_know3h[(size_t)MKNOW*3*SENTD];
__device__ __half g_WsT3h[(size_t)HEADS*HD*3*SENTD];
__device__ __half g_WkT3h[(size_t)HEADS*HD*3*SENTD];
__device__ __half g_S3h [(size_t)HEADS*NSENT*3*HD];
__device__ __half g_Kp3h[(size_t)HEADS*MKNOW*3*HD];
__device__ __half g_knowSh[(size_t)HEADS*SENTD*MKNOW];   // know'/cs, [h][d][m_perm], 64MB
__device__ __half g_WfTh[(size_t)SENTD*HEADS*SENTD];
__device__ __half g_concath[(size_t)NSENT*HEADS*SENTD];
__device__ __half g_Eh[(size_t)HEADS*NSENT*MKNOW];       // exp(scores) fp16 perm16, 268MB
__device__ float  g_colsum[HEADS*MKNOW];
__device__ float  g_csinv[HEADS*MKNOW];

// ---------------- helpers ----------------
__device__ __forceinline__ uint32_t smem_u32(const void* p) {
    uint32_t a;
    asm("{ .reg .u64 t; cvta.to.shared.u64 t, %1; cvt.u32.u64 %0, t; }" : "=r"(a) : "l"(p));
    return a;
}
// within-16 K permutation: k = 8b + 2c + r  ->  4c + 2b + r
__device__ __forceinline__ int perm16(int k) {
    return (k & ~15) | (((k >> 1) & 3) << 2) | (((k >> 3) & 1) << 1) | (k & 1);
}

#define CP_ASYNC16(dst, src) \
    asm volatile("cp.async.cg.shared.global [%0], [%1], 16;" :: "r"(dst), "l"(src) : "memory")
#define CP_COMMIT() asm volatile("cp.async.commit_group;" ::: "memory")
#define CP_WAIT2()  asm volatile("cp.async.wait_group 2;" ::: "memory")

#define MMA_F16(d, a0, a1, a2, a3, b0, b1) \
    asm volatile("mma.sync.aligned.m16n8k16.row.col.f32.f16.f16.f32 " \
        "{%0,%1,%2,%3}, {%4,%5,%6,%7}, {%8,%9}, {%0,%1,%2,%3};" \
        : "+f"((d)[0]), "+f"((d)[1]), "+f"((d)[2]), "+f"((d)[3]) \
        : "r"(a0), "r"(a1), "r"(a2), "r"(a3), "r"(b0), "r"(b1))

enum { MODE_PLAIN = 0, MODE_BIAS = 1, MODE_EXP = 3, MODE_SPLIT3A = 4, MODE_SPLIT3B = 5 };

// ---------------- fp16 mma.sync GEMM ----------------
// C[M x N] (+ per-blockIdx.z batch strides) = A[M x K] * B[N x K]^T.
// A, B: __half, stored with the within-16 K permutation (perm16).
// PR=0 & MODE in {PLAIN,BIAS}: C fp32.
// PR=1: C __half, columns perm16'd + RN-rounded (feeds another GEMM).
// MODE_EXP (+PR=1): C = exp(alpha*acc) fp16 perm16'd + fused fp32 colsum.
// MODE_SPLIT3A/B: C __half [row][3*ldc] hi/lo split triplets, perm16'd, + bias.
//   A-style: [hi|lo|hi], B-style: [hi|hi|lo].
template <int MODE, int PR>
__global__ void __launch_bounds__(256, 2)
hgemm_k(const __half* __restrict__ A, const __half* __restrict__ B, void* __restrict__ Cv,
        int Kn, int lda, int ldb, int ldc,
        long long sA, long long sB, long long sC,
        const float* __restrict__ bias, int sBias, float alpha,
        float* __restrict__ colsum, int sCol)
{
    extern __shared__ char smem[];
    const uint32_t smem_b = smem_u32(smem);
    const int h = blockIdx.z;
    A += (long long)h * sA;
    B += (long long)h * sB;

    const int t = threadIdx.x;
    const int wid = t >> 5, lane = t & 31;
    const int lr = lane >> 2;    // 0..7
    const int lc = lane & 3;     // 0..3
    const int wm = (wid & 1) * 64;
    const int wn = (wid >> 1) * 32;
    const int row0 = blockIdx.y * BM;
    const int col0 = blockIdx.x * BN;
    const int nKT = Kn / BKH;

    const int fr0 = t >> 2, fo = t & 3;
    const int fr1 = (t + 256) >> 2;
    const uint32_t fd0 = (uint32_t)(fo * 16) ^ ((fr0 & 2) << 4);
    const uint32_t fd1 = (uint32_t)(fo * 16) ^ ((fr1 & 2) << 4);

#define LOAD_TILE(kt, s) do { \
    long long _k0 = (long long)(kt) * BKH; \
    uint32_t _sa = smem_b + (s) * STAGE_BYTES; \
    uint32_t _sb = _sa + TILE_BYTES_H; \
    CP_ASYNC16(_sa + fr0 * 64 + fd0, A + (long long)(row0 + fr0) * lda + _k0 + fo * 8); \
    CP_ASYNC16(_sa + fr1 * 64 + fd1, A + (long long)(row0 + fr1) * lda + _k0 + fo * 8); \
    CP_ASYNC16(_sb + fr0 * 64 + fd0, B + (long long)(col0 + fr0) * ldb + _k0 + fo * 8); \
    CP_ASYNC16(_sb + fr1 * 64 + fd1, B + (long long)(col0 + fr1) * ldb + _k0 + fo * 8); \
} while (0)

    float acc[4][4][4];
#pragma unroll
    for (int i = 0; i < 4; i++)
#pragma unroll
        for (int j = 0; j < 4; j++)
#pragma unroll
            for (int q = 0; q < 4; q++) acc[i][j][q] = 0.0f;

    LOAD_TILE(0, 0); CP_COMMIT();
    LOAD_TILE(1, 1); CP_COMMIT();
    LOAD_TILE(2, 2); CP_COMMIT();

    const uint32_t swz = (uint32_t)((lr & 2) << 4);

    for (int it = 0; it < nKT; it++) {
        CP_WAIT2();
        __syncthreads();
        if (it + 3 < nKT) LOAD_TILE(it + 3, (it + 3) & 3);
        CP_COMMIT();

        const char* As = smem + (it & 3) * STAGE_BYTES;
        const char* Bs = As + TILE_BYTES_H;
#pragma unroll
        for (int ks = 0; ks < 2; ks++) {
            const uint32_t koff = (uint32_t)(lc * 8) + (((uint32_t)ks << 5) ^ swz);
            uint2 al[4], ah[4], b[4];
#pragma unroll
            for (int i = 0; i < 4; i++) {
                const int ra = wm + i * 16 + lr;
                al[i] = *(const uint2*)(As + ra * 64 + koff);
                ah[i] = *(const uint2*)(As + (ra + 8) * 64 + koff);
            }
#pragma unroll
            for (int j = 0; j < 4; j++) {
                const int rb = wn + j * 8 + lr;
                b[j] = *(const uint2*)(Bs + rb * 64 + koff);
            }
#pragma unroll
            for (int i = 0; i < 4; i++)
#pragma unroll
                for (int j = 0; j < 4; j++)
                    MMA_F16(acc[i][j], al[i].x, ah[i].x, al[i].y, ah[i].y, b[j].x, b[j].y);
        }
    }

    // epilogue
    const long long co = (long long)h * sC;
    float*  Cf = (float*)Cv + co;
    __half* Ch = (__half*)Cv + co;
    const int ldc3 = 3 * ldc;
#pragma unroll
    for (int j = 0; j < 4; j++) {
        const int c = col0 + wn + j * 8 + lc * 2;
        float b0 = 0.0f, b1 = 0.0f;
        if (MODE == MODE_BIAS || MODE == MODE_SPLIT3A || MODE == MODE_SPLIT3B) {
            b0 = bias[(long long)h * sBias + c];
            b1 = bias[(long long)h * sBias + c + 1];
        }
        float s0 = 0.0f, s1 = 0.0f;
#pragma unroll
        for (int i = 0; i < 4; i++) {
            const int r = row0 + wm + i * 16 + lr;
            float d0 = acc[i][j][0], d1 = acc[i][j][1];
            float d2 = acc[i][j][2], d3 = acc[i][j][3];
            if (MODE == MODE_EXP) {
                d0 = __expf(d0 * alpha); d1 = __expf(d1 * alpha);
                d2 = __expf(d2 * alpha); d3 = __expf(d3 * alpha);
                s0 += d0 + d2; s1 += d1 + d3;
            } else if (MODE == MODE_BIAS || MODE == MODE_SPLIT3A || MODE == MODE_SPLIT3B) {
                d0 += b0; d1 += b1; d2 += b0; d3 += b1;
            }
            if (MODE == MODE_SPLIT3A || MODE == MODE_SPLIT3B) {
                const int pc = perm16(c);
#pragma unroll
                for (int half_i = 0; half_i < 2; half_i++) {
                    const float e0 = half_i ? d2 : d0;
                    const float e1 = half_i ? d3 : d1;
                    const int rr = r + half_i * 8;
                    __half h0 = __float2half_rn(e0), h1 = __float2half_rn(e1);
                    __half l0 = __float2half_rn(e0 - __half2float(h0));
                    __half l1 = __float2half_rn(e1 - __half2float(h1));
                    __half2 hp = __halves2half2(h0, h1);
                    __half2 lp = __halves2half2(l0, l1);
                    __half* p = Ch + (long long)rr * ldc3 + pc;
                    *(__half2*)p = hp;
                    *(__half2*)(p + ldc) = (MODE == MODE_SPLIT3A) ? lp : hp;
                    *(__half2*)(p + 2 * ldc) = (MODE == MODE_SPLIT3A) ? hp : lp;
                }
            } else if (PR) {
                const int pc = perm16(c);   // c even -> perm16(c+1) == pc+1
                *(__half2*)&Ch[(long long)r * ldc + pc] = __floats2half2_rn(d0, d1);
                *(__half2*)&Ch[(long long)(r + 8) * ldc + pc] = __floats2half2_rn(d2, d3);
            } else {
                *(float2*)&Cf[(long long)r * ldc + c]       = make_float2(d0, d1);
                *(float2*)&Cf[(long long)(r + 8) * ldc + c] = make_float2(d2, d3);
            }
        }
        if (MODE == MODE_EXP) {
#pragma unroll
            for (int msk = 4; msk <= 16; msk <<= 1) {
                s0 += __shfl_xor_sync(0xFFFFFFFFu, s0, msk);
                s1 += __shfl_xor_sync(0xFFFFFFFFu, s1, msk);
            }
            if (lane < 4) {
                atomicAdd(&colsum[(long long)h * sCol + c], s0);
                atomicAdd(&colsum[(long long)h * sCol + c + 1], s1);
            }
        }
    }
}

// ---------------- prep / softmax kernels ----------------

// fp32 [R,C] -> half [R,3C] perm16'd: a_style=1 -> [hi|lo|hi], 0 -> [hi|hi|lo]
__global__ void split3h_k(const float* __restrict__ in, __half* __restrict__ out,
                          int C, long long total, int a_style) {
    for (long long i = (long long)blockIdx.x * blockDim.x + threadIdx.x;
         i < total; i += (long long)gridDim.x * blockDim.x) {
        long long r = i / C;
        int c = (int)(i - r * C);
        float x = in[i];
        __half hi = __float2half_rn(x);
        __half lo = __float2half_rn(x - __half2float(hi));
        __half* o = out + r * 3LL * C;
        int cp = perm16(c);
        o[cp] = hi;
        o[C + cp] = a_style ? lo : hi;
        o[2 * C + cp] = a_style ? hi : lo;
    }
}

// W [h][D][E] -> half out [h][E][3D] B-style ([hi|hi|lo]), perm16'd
__global__ void split3Th_k(const float* __restrict__ in, __half* __restrict__ out,
                           int D, int E) {
    __shared__ float tile[32][33];
    const int h = blockIdx.z;
    const int e0 = blockIdx.x * 32, d0 = blockIdx.y * 32;
    in += (size_t)h * D * E;
    out += (size_t)h * E * 3 * D;
    const int x = threadIdx.x, y = threadIdx.y;
#pragma unroll
    for (int j = 0; j < 32; j += 8)
        tile[y + j][x] = in[(long long)(d0 + y + j) * E + e0 + x];
    __syncthreads();
#pragma unroll
    for (int j = 0; j < 32; j += 8) {
        float v = tile[x][y + j];
        __half hi = __float2half_rn(v);
        __half lo = __float2half_rn(v - __half2float(hi));
        long long o = (long long)(e0 + y + j) * 3 * D + d0 + perm16(x);
        out[o] = hi;
        out[o + D] = hi;
        out[o + 2 * D] = lo;
    }
}

// fp32 [R,C] -> half [C,R] RN-rounded, out-col perm16'd (for W_f)
__global__ void transposeh_k(const float* __restrict__ in, __half* __restrict__ out,
                             int R, int C) {
    __shared__ float tile[32][33];
    const int c0 = blockIdx.x * 32, r0 = blockIdx.y * 32;
    const int x = threadIdx.x, y = threadIdx.y;
#pragma unroll
    for (int j = 0; j < 32; j += 8)
        tile[y + j][x] = in[(long long)(r0 + y + j) * C + c0 + x];
    __syncthreads();
#pragma unroll
    for (int j = 0; j < 32; j += 8)
        out[(long long)(c0 + y + j) * R + r0 + perm16(x)] =
            __float2half_rn(tile[x][y + j]);
}

__global__ void zero_colsum_k() {
    int i = blockIdx.x * blockDim.x + threadIdx.x;
    if (i < HEADS * MKNOW) g_colsum[i] = 0.0f;
}

__global__ void csinv_k() {
    int i = blockIdx.x * blockDim.x + threadIdx.x;
    if (i < HEADS * MKNOW) g_csinv[i] = 1.0f / g_colsum[i];
}

// weights output: wout[h][n][m] = half(E)[h][n][m] * csinv[h][m], un-permuting columns
__global__ void normalizeE_k(const __half* __restrict__ E, float* __restrict__ wout) {
    const long long ngroups = (long long)HEADS * NSENT * (MKNOW / 16);
    for (long long g = (long long)blockIdx.x * blockDim.x + threadIdx.x;
         g < ngroups; g += (long long)gridDim.x * blockDim.x) {
        const int grp = (int)(g & (MKNOW / 16 - 1));
        const long long row = g >> 8;            // h*NSENT + n
        const int h = (int)(row >> 12);
        const int m0 = grp * 16;
        const __half* ep = E + row * MKNOW + m0;
        __half e[16];
        *(uint4*)&e[0] = *(const uint4*)ep;
        *(uint4*)&e[8] = *(const uint4*)(ep + 8);
        const float* ci = &g_csinv[h * MKNOW + m0];
        float o[16];
#pragma unroll
        for (int j = 0; j < 16; j++)
            o[j] = __half2float(e[perm16(j)]) * ci[j];
        float* wp = wout + row * MKNOW + m0;
#pragma unroll
        for (int q = 0; q < 4; q++)
            *(float4*)(wp + q * 4) = make_float4(o[q*4], o[q*4+1], o[q*4+2], o[q*4+3]);
    }
}

// know [m][d] fp32 -> out[h][d][perm16(m)] = half(know[m][d] * csinv[h][m])
__global__ void transposeScaleh_k(const float* __restrict__ know, __half* __restrict__ out) {
    __shared__ float tile[32][33];
    const int d0 = blockIdx.x * 32, m0 = blockIdx.y * 32;
    const int x = threadIdx.x, y = threadIdx.y;
#pragma unroll
    for (int j = 0; j < 32; j += 8)
        tile[y + j][x] = know[(long long)(m0 + y + j) * SENTD + d0 + x];
    __syncthreads();
    const int pmx = (x & 16) | (perm16(x & 15));
#pragma unroll
    for (int h = 0; h < HEADS; h++) {
        const float inv = g_csinv[h * MKNOW + m0 + x];
#pragma unroll
        for (int j = 0; j < 32; j += 8) {
            float v = tile[x][y + j] * inv;
            out[((size_t)h * SENTD + d0 + y + j) * MKNOW + m0 + pmx] = __float2half_rn(v);
        }
    }
}

// ---------------- launch ----------------
extern "C" void kernel_launch(void* const* d_in, const int* in_sizes, int n_in,
                              void* d_out, int out_size)
{
    const float* sentences = (const float*)d_in[0];
    const float* knowledge = (const float*)d_in[1];
    const float* W_s = (const float*)d_in[2];
    const float* b_s = (const float*)d_in[3];
    const float* W_k = (const float*)d_in[4];
    const float* b_k = (const float*)d_in[5];
    const float* W_f = (const float*)d_in[6];
    const float* b_f = (const float*)d_in[7];

    float* out0 = (float*)d_out;                        // [4096,1024]
    float* wout = out0 + (long long)NSENT * SENTD;      // [8*4096,4096]

    __half* gSent3 = nullptr; cudaGetSymbolAddress((void**)&gSent3, g_sent3h);
    __half* gKnow3 = nullptr; cudaGetSymbolAddress((void**)&gKnow3, g_know3h);
    __half* gWsT3 = nullptr;  cudaGetSymbolAddress((void**)&gWsT3, g_WsT3h);
    __half* gWkT3 = nullptr;  cudaGetSymbolAddress((void**)&gWkT3, g_WkT3h);
    __half* gS3 = nullptr;    cudaGetSymbolAddress((void**)&gS3, g_S3h);
    __half* gKp3 = nullptr;   cudaGetSymbolAddress((void**)&gKp3, g_Kp3h);
    __half* gKnS = nullptr;   cudaGetSymbolAddress((void**)&gKnS, g_knowSh);
    __half* gWfT = nullptr;   cudaGetSymbolAddress((void**)&gWfT, g_WfTh);
    __half* gCc = nullptr;    cudaGetSymbolAddress((void**)&gCc, g_concath);
    __half* gE = nullptr;     cudaGetSymbolAddress((void**)&gE, g_Eh);
    float* gCs = nullptr;     cudaGetSymbolAddress((void**)&gCs, g_colsum);

    cudaFuncSetAttribute(hgemm_k<MODE_SPLIT3A, 0>, cudaFuncAttributeMaxDynamicSharedMemorySize, SMEM_BYTES);
    cudaFuncSetAttribute(hgemm_k<MODE_SPLIT3B, 0>, cudaFuncAttributeMaxDynamicSharedMemorySize, SMEM_BYTES);
    cudaFuncSetAttribute(hgemm_k<MODE_EXP, 1>,     cudaFuncAttributeMaxDynamicSharedMemorySize, SMEM_BYTES);
    cudaFuncSetAttribute(hgemm_k<MODE_PLAIN, 1>,   cudaFuncAttributeMaxDynamicSharedMemorySize, SMEM_BYTES);
    cudaFuncSetAttribute(hgemm_k<MODE_BIAS, 0>,    cudaFuncAttributeMaxDynamicSharedMemorySize, SMEM_BYTES);

    const float inv_sqrt_hd = 0.08838834764831845f;

    // --- prep ---
    split3h_k<<<1024, 256>>>(sentences, gSent3, SENTD, (long long)NSENT * SENTD, 1);
    split3h_k<<<1024, 256>>>(knowledge, gKnow3, SENTD, (long long)MKNOW * SENTD, 1);
    split3Th_k<<<dim3(HD / 32, SENTD / 32, HEADS), dim3(32, 8)>>>(W_s, gWsT3, SENTD, HD);
    split3Th_k<<<dim3(HD / 32, SENTD / 32, HEADS), dim3(32, 8)>>>(W_k, gWkT3, SENTD, HD);
    transposeh_k<<<dim3(SENTD / 32, (HEADS * SENTD) / 32), dim3(32, 8)>>>(W_f, gWfT, HEADS * SENTD, SENTD);
    zero_colsum_k<<<(HEADS * MKNOW + 255) / 256, 256>>>();

    // --- projections (split fp16, K=3072) -> fused hi/lo split outputs ---
    hgemm_k<MODE_SPLIT3A, 0><<<dim3(1, NSENT / BM, HEADS), 256, SMEM_BYTES>>>(
        gSent3, gWsT3, gS3, 3 * SENTD, 3 * SENTD, 3 * SENTD, HD,
        0LL, (long long)HD * 3 * SENTD, (long long)NSENT * 3 * HD, b_s, HD, 0.0f, nullptr, 0);
    hgemm_k<MODE_SPLIT3B, 0><<<dim3(1, MKNOW / BM, HEADS), 256, SMEM_BYTES>>>(
        gKnow3, gWkT3, gKp3, 3 * SENTD, 3 * SENTD, 3 * SENTD, HD,
        0LL, (long long)HD * 3 * SENTD, (long long)MKNOW * 3 * HD, b_k, HD, 0.0f, nullptr, 0);

    // --- scores (split fp16, K=384) -> E fp16 perm16 + fused colsum ---
    hgemm_k<MODE_EXP, 1><<<dim3(MKNOW / BN, NSENT / BM, HEADS), 256, SMEM_BYTES>>>(
        gS3, gKp3, gE, 3 * HD, 3 * HD, 3 * HD, MKNOW,
        (long long)NSENT * 3 * HD, (long long)MKNOW * 3 * HD, (long long)NSENT * MKNOW,
        nullptr, 0, inv_sqrt_hd, gCs, MKNOW);

    // --- softmax: inverse sums, weights output, scaled knowledge ---
    csinv_k<<<(HEADS * MKNOW + 255) / 256, 256>>>();
    normalizeE_k<<<8192, 256>>>(gE, wout);
    transposeScaleh_k<<<dim3(SENTD / 32, MKNOW / 32), dim3(32, 8)>>>(knowledge, gKnS);

    // --- attn: E[h] @ know'[h]^T -> concat half (perm16'd cols) ---
    hgemm_k<MODE_PLAIN, 1><<<dim3(SENTD / BN, NSENT / BM, HEADS), 256, SMEM_BYTES>>>(
        gE, gKnS, gCc, MKNOW, MKNOW, MKNOW, HEADS * SENTD,
        (long long)NSENT * MKNOW, (long long)SENTD * MKNOW, (long long)SENTD,
        nullptr, 0, 0.0f, nullptr, 0);

    // --- final: concat @ W_f + b_f (fp16, K=8192) -> fp32 out ---
    hgemm_k<MODE_BIAS, 0><<<dim3(SENTD / BN, NSENT / BM, 1), 256, SMEM_BYTES>>>(
        gCc, gWfT, out0, HEADS * SENTD, HEADS * SENTD, HEADS * SENTD, SENTD,
        0LL, 0LL, 0LL, b_f, 0, 0.0f, nullptr, 0);
}

// round 8
// speedup vs baseline: 1.0753x; 1.0753x over previous
#include <cuda_runtime.h>
#include <cuda_fp16.h>
#include <cstdint>
#include <math.h>

// ---------------- problem constants ----------------
#define NSENT 4096
#define MKNOW 4096
#define HEADS 8
#define SENTD 1024
#define HD    128

// ---------------- GEMM tile config ----------------
#define BM 128
#define BN 128
#define BKH 32                          // k halves per stage (2 mma k16 steps)
#define TILE_BYTES_H (128 * 64)         // 128 rows x 64B
#define STAGE_BYTES (2 * TILE_BYTES_H)  // A + B = 16 KB
#define STAGES 4
#define SMEM_BYTES (STAGES * STAGE_BYTES)   // 64 KB -> 2 CTAs/SM

// ---------------- scratch (static device arrays) ----------------
__device__ __half g_sent3h[(size_t)NSENT*3*SENTD];
__device__ __half g_know3h[(size_t)MKNOW*3*SENTD];
__device__ __half g_WsT3h[(size_t)HEADS*HD*3*SENTD];
__device__ __half g_WkT3h[(size_t)HEADS*HD*3*SENTD];
__device__ __half g_S3h [(size_t)HEADS*NSENT*3*HD];
__device__ __half g_Kp3h[(size_t)HEADS*MKNOW*3*HD];
__device__ __half g_knowTh[(size_t)SENTD*MKNOW];
__device__ __half g_WfTh[(size_t)SENTD*HEADS*SENTD];
__device__ __half g_concath[(size_t)NSENT*HEADS*SENTD];
__device__ __half g_wrndh[(size_t)HEADS*NSENT*MKNOW];
__device__ float  g_colsum[HEADS*MKNOW];

// ---------------- helpers ----------------
__device__ __forceinline__ uint32_t smem_u32(const void* p) {
    uint32_t a;
    asm("{ .reg .u64 t; cvta.to.shared.u64 t, %1; cvt.u32.u64 %0, t; }" : "=r"(a) : "l"(p));
    return a;
}
// within-16 K permutation: k = 8b + 2c + r  ->  4c + 2b + r
__device__ __forceinline__ int perm16(int k) {
    return (k & ~15) | (((k >> 1) & 3) << 2) | (((k >> 3) & 1) << 1) | (k & 1);
}

#define CP_ASYNC16(dst, src) \
    asm volatile("cp.async.cg.shared.global [%0], [%1], 16;" :: "r"(dst), "l"(src) : "memory")
#define CP_COMMIT() asm volatile("cp.async.commit_group;" ::: "memory")
#define CP_WAIT2()  asm volatile("cp.async.wait_group 2;" ::: "memory")

#define MMA_F16(d, a0, a1, a2, a3, b0, b1) \
    asm volatile("mma.sync.aligned.m16n8k16.row.col.f32.f16.f16.f32 " \
        "{%0,%1,%2,%3}, {%4,%5,%6,%7}, {%8,%9}, {%0,%1,%2,%3};" \
        : "+f"((d)[0]), "+f"((d)[1]), "+f"((d)[2]), "+f"((d)[3]) \
        : "r"(a0), "r"(a1), "r"(a2), "r"(a3), "r"(b0), "r"(b1))

enum { MODE_PLAIN = 0, MODE_BIAS = 1, MODE_EXP = 3, MODE_SPLIT3A = 4, MODE_SPLIT3B = 5 };

// ---------------- fp16 mma.sync GEMM ----------------
// C[M x N] (+ per-blockIdx.z batch strides) = A[M x K] * B[N x K]^T.
// A, B: __half, stored with the within-16 K permutation (perm16).
// PR=0 & MODE in {PLAIN,BIAS,EXP}: C fp32 (EXP: exp(alpha*acc) + fused colsum).
// PR=1: C __half, columns perm16'd + RN-rounded (feeds another GEMM).
// MODE_SPLIT3A/B: C __half [row][3*ldc] hi/lo split triplets, perm16'd, + bias.
template <int MODE, int PR>
__global__ void __launch_bounds__(256, 2)
hgemm_k(const __half* __restrict__ A, const __half* __restrict__ B, void* __restrict__ Cv,
        int Kn, int lda, int ldb, int ldc,
        long long sA, long long sB, long long sC,
        const float* __restrict__ bias, int sBias, float alpha,
        float* __restrict__ colsum, int sCol)
{
    extern __shared__ char smem[];
    const uint32_t smem_b = smem_u32(smem);
    const int h = blockIdx.z;
    A += (long long)h * sA;
    B += (long long)h * sB;

    const int t = threadIdx.x;
    const int wid = t >> 5, lane = t & 31;
    const int lr = lane >> 2;    // 0..7
    const int lc = lane & 3;     // 0..3
    const int wm = (wid & 1) * 64;
    const int wn = (wid >> 1) * 32;
    const int row0 = blockIdx.y * BM;
    const int col0 = blockIdx.x * BN;
    const int nKT = Kn / BKH;

    const int fr0 = t >> 2, fo = t & 3;
    const int fr1 = (t + 256) >> 2;
    const uint32_t fd0 = (uint32_t)(fo * 16) ^ ((fr0 & 2) << 4);
    const uint32_t fd1 = (uint32_t)(fo * 16) ^ ((fr1 & 2) << 4);

#define LOAD_TILE(kt, s) do { \
    long long _k0 = (long long)(kt) * BKH; \
    uint32_t _sa = smem_b + (s) * STAGE_BYTES; \
    uint32_t _sb = _sa + TILE_BYTES_H; \
    CP_ASYNC16(_sa + fr0 * 64 + fd0, A + (long long)(row0 + fr0) * lda + _k0 + fo * 8); \
    CP_ASYNC16(_sa + fr1 * 64 + fd1, A + (long long)(row0 + fr1) * lda + _k0 + fo * 8); \
    CP_ASYNC16(_sb + fr0 * 64 + fd0, B + (long long)(col0 + fr0) * ldb + _k0 + fo * 8); \
    CP_ASYNC16(_sb + fr1 * 64 + fd1, B + (long long)(col0 + fr1) * ldb + _k0 + fo * 8); \
} while (0)

    float acc[4][4][4];
#pragma unroll
    for (int i = 0; i < 4; i++)
#pragma unroll
        for (int j = 0; j < 4; j++)
#pragma unroll
            for (int q = 0; q < 4; q++) acc[i][j][q] = 0.0f;

    LOAD_TILE(0, 0); CP_COMMIT();
    LOAD_TILE(1, 1); CP_COMMIT();
    LOAD_TILE(2, 2); CP_COMMIT();

    const uint32_t swz = (uint32_t)((lr & 2) << 4);

    for (int it = 0; it < nKT; it++) {
        CP_WAIT2();
        __syncthreads();
        if (it + 3 < nKT) LOAD_TILE(it + 3, (it + 3) & 3);
        CP_COMMIT();

        const char* As = smem + (it & 3) * STAGE_BYTES;
        const char* Bs = As + TILE_BYTES_H;
#pragma unroll
        for (int ks = 0; ks < 2; ks++) {
            const uint32_t koff = (uint32_t)(lc * 8) + (((uint32_t)ks << 5) ^ swz);
            uint2 al[4], ah[4], b[4];
#pragma unroll
            for (int i = 0; i < 4; i++) {
                const int ra = wm + i * 16 + lr;
                al[i] = *(const uint2*)(As + ra * 64 + koff);
                ah[i] = *(const uint2*)(As + (ra + 8) * 64 + koff);
            }
#pragma unroll
            for (int j = 0; j < 4; j++) {
                const int rb = wn + j * 8 + lr;
                b[j] = *(const uint2*)(Bs + rb * 64 + koff);
            }
#pragma unroll
            for (int i = 0; i < 4; i++)
#pragma unroll
                for (int j = 0; j < 4; j++)
                    MMA_F16(acc[i][j], al[i].x, ah[i].x, al[i].y, ah[i].y, b[j].x, b[j].y);
        }
    }

    // epilogue
    const long long co = (long long)h * sC;
    float*  Cf = (float*)Cv + co;
    __half* Ch = (__half*)Cv + co;
    const int ldc3 = 3 * ldc;
#pragma unroll
    for (int j = 0; j < 4; j++) {
        const int c = col0 + wn + j * 8 + lc * 2;
        float b0 = 0.0f, b1 = 0.0f;
        if (MODE == MODE_BIAS || MODE == MODE_SPLIT3A || MODE == MODE_SPLIT3B) {
            b0 = bias[(long long)h * sBias + c];
            b1 = bias[(long long)h * sBias + c + 1];
        }
        float s0 = 0.0f, s1 = 0.0f;
#pragma unroll
        for (int i = 0; i < 4; i++) {
            const int r = row0 + wm + i * 16 + lr;
            float d0 = acc[i][j][0], d1 = acc[i][j][1];
            float d2 = acc[i][j][2], d3 = acc[i][j][3];
            if (MODE == MODE_EXP) {
                d0 = __expf(d0 * alpha); d1 = __expf(d1 * alpha);
                d2 = __expf(d2 * alpha); d3 = __expf(d3 * alpha);
                s0 += d0 + d2; s1 += d1 + d3;
            } else if (MODE == MODE_BIAS || MODE == MODE_SPLIT3A || MODE == MODE_SPLIT3B) {
                d0 += b0; d1 += b1; d2 += b0; d3 += b1;
            }
            if (MODE == MODE_SPLIT3A || MODE == MODE_SPLIT3B) {
                const int pc = perm16(c);
#pragma unroll
                for (int half_i = 0; half_i < 2; half_i++) {
                    const float e0 = half_i ? d2 : d0;
                    const float e1 = half_i ? d3 : d1;
                    const int rr = r + half_i * 8;
                    __half h0 = __float2half_rn(e0), h1 = __float2half_rn(e1);
                    __half l0 = __float2half_rn(e0 - __half2float(h0));
                    __half l1 = __float2half_rn(e1 - __half2float(h1));
                    __half2 hp = __halves2half2(h0, h1);
                    __half2 lp = __halves2half2(l0, l1);
                    __half* p = Ch + (long long)rr * ldc3 + pc;
                    *(__half2*)p = hp;
                    *(__half2*)(p + ldc) = (MODE == MODE_SPLIT3A) ? lp : hp;
                    *(__half2*)(p + 2 * ldc) = (MODE == MODE_SPLIT3A) ? hp : lp;
                }
            } else if (PR) {
                const int pc = perm16(c);   // c even -> perm16(c+1) == pc+1
                *(__half2*)&Ch[(long long)r * ldc + pc] = __floats2half2_rn(d0, d1);
                *(__half2*)&Ch[(long long)(r + 8) * ldc + pc] = __floats2half2_rn(d2, d3);
            } else {
                *(float2*)&Cf[(long long)r * ldc + c]       = make_float2(d0, d1);
                *(float2*)&Cf[(long long)(r + 8) * ldc + c] = make_float2(d2, d3);
            }
        }
        if (MODE == MODE_EXP) {
#pragma unroll
            for (int msk = 4; msk <= 16; msk <<= 1) {
                s0 += __shfl_xor_sync(0xFFFFFFFFu, s0, msk);
                s1 += __shfl_xor_sync(0xFFFFFFFFu, s1, msk);
            }
            if (lane < 4) {
                atomicAdd(&colsum[(long long)h * sCol + c], s0);
                atomicAdd(&colsum[(long long)h * sCol + c + 1], s1);
            }
        }
    }
}

// ---------------- prep / softmax kernels ----------------

// fp32 [R,C] -> half [R,3C] perm16'd: a_style=1 -> [hi|lo|hi], 0 -> [hi|hi|lo]
__global__ void split3h_k(const float* __restrict__ in, __half* __restrict__ out,
                          int C, long long total, int a_style) {
    for (long long i = (long long)blockIdx.x * blockDim.x + threadIdx.x;
         i < total; i += (long long)gridDim.x * blockDim.x) {
        long long r = i / C;
        int c = (int)(i - r * C);
        float x = in[i];
        __half hi = __float2half_rn(x);
        __half lo = __float2half_rn(x - __half2float(hi));
        __half* o = out + r * 3LL * C;
        int cp = perm16(c);
        o[cp] = hi;
        o[C + cp] = a_style ? lo : hi;
        o[2 * C + cp] = a_style ? hi : lo;
    }
}

// W [h][D][E] -> half out [h][E][3D] B-style ([hi|hi|lo]), perm16'd
__global__ void split3Th_k(const float* __restrict__ in, __half* __restrict__ out,
                           int D, int E) {
    __shared__ float tile[32][33];
    const int h = blockIdx.z;
    const int e0 = blockIdx.x * 32, d0 = blockIdx.y * 32;
    in += (size_t)h * D * E;
    out += (size_t)h * E * 3 * D;
    const int x = threadIdx.x, y = threadIdx.y;
#pragma unroll
    for (int j = 0; j < 32; j += 8)
        tile[y + j][x] = in[(long long)(d0 + y + j) * E + e0 + x];
    __syncthreads();
#pragma unroll
    for (int j = 0; j < 32; j += 8) {
        float v = tile[x][y + j];
        __half hi = __float2half_rn(v);
        __half lo = __float2half_rn(v - __half2float(hi));
        long long o = (long long)(e0 + y + j) * 3 * D + d0 + perm16(x);
        out[o] = hi;
        out[o + D] = hi;
        out[o + 2 * D] = lo;
    }
}

// fp32 [R,C] -> half [C,R] RN-rounded, out-col perm16'd
__global__ void transposeh_k(const float* __restrict__ in, __half* __restrict__ out,
                             int R, int C) {
    __shared__ float tile[32][33];
    const int c0 = blockIdx.x * 32, r0 = blockIdx.y * 32;
    const int x = threadIdx.x, y = threadIdx.y;
#pragma unroll
    for (int j = 0; j < 32; j += 8)
        tile[y + j][x] = in[(long long)(r0 + y + j) * C + c0 + x];
    __syncthreads();
#pragma unroll
    for (int j = 0; j < 32; j += 8)
        out[(long long)(c0 + y + j) * R + r0 + perm16(x)] =
            __float2half_rn(tile[x][y + j]);
}

__global__ void zero_colsum_k() {
    int i = blockIdx.x * blockDim.x + threadIdx.x;
    if (i < HEADS * MKNOW) g_colsum[i] = 0.0f;
}

// w[h,n,m] /= colsum[h,m] in place (exact fp32 output); also write RN-rounded,
// perm16'd half copy for the attn GEMM's A operand.
__global__ void normalize_k(float* __restrict__ w, __half* __restrict__ wr) {
    const long long total4 = (long long)HEADS * NSENT * MKNOW / 4;
    for (long long i = (long long)blockIdx.x * blockDim.x + threadIdx.x;
         i < total4; i += (long long)gridDim.x * blockDim.x) {
        long long e = i << 2;
        int h = (int)(e >> 24);
        int m = (int)(e & (MKNOW - 1));
        const float* cs = &g_colsum[h * MKNOW + m];
        float4 v = ((float4*)w)[i];
        v.x /= cs[0]; v.y /= cs[1]; v.z /= cs[2]; v.w /= cs[3];
        ((float4*)w)[i] = v;
        long long rowbase = e - m;
        wr[rowbase + perm16(m)]     = __float2half_rn(v.x);
        wr[rowbase + perm16(m + 1)] = __float2half_rn(v.y);
        wr[rowbase + perm16(m + 2)] = __float2half_rn(v.z);
        wr[rowbase + perm16(m + 3)] = __float2half_rn(v.w);
    }
}

// ---------------- launch ----------------
extern "C" void kernel_launch(void* const* d_in, const int* in_sizes, int n_in,
                              void* d_out, int out_size)
{
    const float* sentences = (const float*)d_in[0];
    const float* knowledge = (const float*)d_in[1];
    const float* W_s = (const float*)d_in[2];
    const float* b_s = (const float*)d_in[3];
    const float* W_k = (const float*)d_in[4];
    const float* b_k = (const float*)d_in[5];
    const float* W_f = (const float*)d_in[6];
    const float* b_f = (const float*)d_in[7];

    float* out0 = (float*)d_out;                        // [4096,1024]
    float* wout = out0 + (long long)NSENT * SENTD;      // [8*4096,4096]

    __half* gSent3 = nullptr; cudaGetSymbolAddress((void**)&gSent3, g_sent3h);
    __half* gKnow3 = nullptr; cudaGetSymbolAddress((void**)&gKnow3, g_know3h);
    __half* gWsT3 = nullptr;  cudaGetSymbolAddress((void**)&gWsT3, g_WsT3h);
    __half* gWkT3 = nullptr;  cudaGetSymbolAddress((void**)&gWkT3, g_WkT3h);
    __half* gS3 = nullptr;    cudaGetSymbolAddress((void**)&gS3, g_S3h);
    __half* gKp3 = nullptr;   cudaGetSymbolAddress((void**)&gKp3, g_Kp3h);
    __half* gKnT = nullptr;   cudaGetSymbolAddress((void**)&gKnT, g_knowTh);
    __half* gWfT = nullptr;   cudaGetSymbolAddress((void**)&gWfT, g_WfTh);
    __half* gCc = nullptr;    cudaGetSymbolAddress((void**)&gCc, g_concath);
    __half* gWr = nullptr;    cudaGetSymbolAddress((void**)&gWr, g_wrndh);
    float* gCs = nullptr;     cudaGetSymbolAddress((void**)&gCs, g_colsum);

    cudaFuncSetAttribute(hgemm_k<MODE_SPLIT3A, 0>, cudaFuncAttributeMaxDynamicSharedMemorySize, SMEM_BYTES);
    cudaFuncSetAttribute(hgemm_k<MODE_SPLIT3B, 0>, cudaFuncAttributeMaxDynamicSharedMemorySize, SMEM_BYTES);
    cudaFuncSetAttribute(hgemm_k<MODE_EXP, 0>,     cudaFuncAttributeMaxDynamicSharedMemorySize, SMEM_BYTES);
    cudaFuncSetAttribute(hgemm_k<MODE_PLAIN, 1>,   cudaFuncAttributeMaxDynamicSharedMemorySize, SMEM_BYTES);
    cudaFuncSetAttribute(hgemm_k<MODE_BIAS, 0>,    cudaFuncAttributeMaxDynamicSharedMemorySize, SMEM_BYTES);

    const float inv_sqrt_hd = 0.08838834764831845f;

    // --- prep ---
    split3h_k<<<1024, 256>>>(sentences, gSent3, SENTD, (long long)NSENT * SENTD, 1);
    split3h_k<<<1024, 256>>>(knowledge, gKnow3, SENTD, (long long)MKNOW * SENTD, 1);
    split3Th_k<<<dim3(HD / 32, SENTD / 32, HEADS), dim3(32, 8)>>>(W_s, gWsT3, SENTD, HD);
    split3Th_k<<<dim3(HD / 32, SENTD / 32, HEADS), dim3(32, 8)>>>(W_k, gWkT3, SENTD, HD);
    transposeh_k<<<dim3(SENTD / 32, MKNOW / 32), dim3(32, 8)>>>(knowledge, gKnT, MKNOW, SENTD);
    transposeh_k<<<dim3(SENTD / 32, (HEADS * SENTD) / 32), dim3(32, 8)>>>(W_f, gWfT, HEADS * SENTD, SENTD);
    zero_colsum_k<<<(HEADS * MKNOW + 255) / 256, 256>>>();

    // --- projections (split fp16, K=3072) -> fused hi/lo split outputs ---
    hgemm_k<MODE_SPLIT3A, 0><<<dim3(1, NSENT / BM, HEADS), 256, SMEM_BYTES>>>(
        gSent3, gWsT3, gS3, 3 * SENTD, 3 * SENTD, 3 * SENTD, HD,
        0LL, (long long)HD * 3 * SENTD, (long long)NSENT * 3 * HD, b_s, HD, 0.0f, nullptr, 0);
    hgemm_k<MODE_SPLIT3B, 0><<<dim3(1, MKNOW / BM, HEADS), 256, SMEM_BYTES>>>(
        gKnow3, gWkT3, gKp3, 3 * SENTD, 3 * SENTD, 3 * SENTD, HD,
        0LL, (long long)HD * 3 * SENTD, (long long)MKNOW * 3 * HD, b_k, HD, 0.0f, nullptr, 0);

    // --- scores (split fp16, K=384) -> exp -> fp32 weights output; fused colsum ---
    hgemm_k<MODE_EXP, 0><<<dim3(MKNOW / BN, NSENT / BM, HEADS), 256, SMEM_BYTES>>>(
        gS3, gKp3, wout, 3 * HD, 3 * HD, 3 * HD, MKNOW,
        (long long)NSENT * 3 * HD, (long long)MKNOW * 3 * HD, (long long)NSENT * MKNOW,
        nullptr, 0, inv_sqrt_hd, gCs, MKNOW);

    // --- softmax normalize (exact fp32) + rounded/perm16'd half copy ---
    normalize_k<<<4096, 256>>>(wout, gWr);

    // --- attn: wrnd[h] @ knowT^T -> concat half (perm16'd cols for final GEMM) ---
    hgemm_k<MODE_PLAIN, 1><<<dim3(SENTD / BN, NSENT / BM, HEADS), 256, SMEM_BYTES>>>(
        gWr, gKnT, gCc, MKNOW, MKNOW, MKNOW, HEADS * SENTD,
        (long long)NSENT * MKNOW, 0LL, (long long)SENTD, nullptr, 0, 0.0f, nullptr, 0);

    // --- final: concat @ W_f + b_f (fp16, K=8192) -> fp32 out ---
    hgemm_k<MODE_BIAS, 0><<<dim3(SENTD / BN, NSENT / BM, 1), 256, SMEM_BYTES>>>(
        gCc, gWfT, out0, HEADS * SENTD, HEADS * SENTD, HEADS * SENTD, SENTD,
        0LL, 0LL, 0LL, b_f, 0, 0.0f, nullptr, 0);
}

// round 9
// speedup vs baseline: 1.3078x; 1.2162x over previous
#include <cuda_runtime.h>
#include <cuda_fp16.h>
#include <cstdint>
#include <math.h>

// ---------------- problem constants ----------------
#define NSENT 4096
#define MKNOW 4096
#define HEADS 8
#define SENTD 1024
#define HD    128

// ---------------- GEMM tile config ----------------
#define BM 128
#define BN 128
#define BKH 32                          // k halves per stage (2 mma k16 steps)
#define TILE_BYTES_H (128 * 64)         // 128 rows x 64B
#define STAGE_BYTES (2 * TILE_BYTES_H)  // A + B = 16 KB
#define STAGES 4
#define SMEM_BYTES (STAGES * STAGE_BYTES)   // 64 KB -> 2 CTAs/SM

// ---------------- scratch (static device arrays) ----------------
__device__ __half g_sentH[(size_t)NSENT*SENTD];
__device__ __half g_knowH[(size_t)MKNOW*SENTD];
__device__ __half g_WsTh[(size_t)HEADS*HD*SENTD];
__device__ __half g_WkTh[(size_t)HEADS*HD*SENTD];
__device__ __half g_Sh [(size_t)HEADS*NSENT*HD];
__device__ __half g_Kph[(size_t)HEADS*MKNOW*HD];
__device__ __half g_knowTh[(size_t)SENTD*MKNOW];
__device__ __half g_WfTh[(size_t)SENTD*HEADS*SENTD];
__device__ __half g_concath[(size_t)NSENT*HEADS*SENTD];
__device__ __half g_wrndh[(size_t)HEADS*NSENT*MKNOW];
__device__ float  g_colsum[HEADS*MKNOW];

// ---------------- helpers ----------------
__device__ __forceinline__ uint32_t smem_u32(const void* p) {
    uint32_t a;
    asm("{ .reg .u64 t; cvta.to.shared.u64 t, %1; cvt.u32.u64 %0, t; }" : "=r"(a) : "l"(p));
    return a;
}
// within-16 K permutation: k = 8b + 2c + r  ->  4c + 2b + r
__device__ __forceinline__ int perm16(int k) {
    return (k & ~15) | (((k >> 1) & 3) << 2) | (((k >> 3) & 1) << 1) | (k & 1);
}

#define CP_ASYNC16(dst, src) \
    asm volatile("cp.async.cg.shared.global [%0], [%1], 16;" :: "r"(dst), "l"(src) : "memory")
#define CP_COMMIT() asm volatile("cp.async.commit_group;" ::: "memory")
#define CP_WAIT2()  asm volatile("cp.async.wait_group 2;" ::: "memory")

#define MMA_F16(d, a0, a1, a2, a3, b0, b1) \
    asm volatile("mma.sync.aligned.m16n8k16.row.col.f32.f16.f16.f32 " \
        "{%0,%1,%2,%3}, {%4,%5,%6,%7}, {%8,%9}, {%0,%1,%2,%3};" \
        : "+f"((d)[0]), "+f"((d)[1]), "+f"((d)[2]), "+f"((d)[3]) \
        : "r"(a0), "r"(a1), "r"(a2), "r"(a3), "r"(b0), "r"(b1))

enum { MODE_PLAIN = 0, MODE_BIAS = 1, MODE_EXP = 3 };

// ---------------- fp16 mma.sync GEMM ----------------
// C[M x N] (+ per-blockIdx.z batch strides) = A[M x K] * B[N x K]^T.
// A, B: __half, stored with the within-16 K permutation (perm16).
// PR=0: C fp32 (MODE_EXP: exp(alpha*acc) + fused colsum; MODE_BIAS: +bias).
// PR=1: C __half, columns perm16'd + RN-rounded (feeds another GEMM); bias ok.
template <int MODE, int PR>
__global__ void __launch_bounds__(256, 2)
hgemm_k(const __half* __restrict__ A, const __half* __restrict__ B, void* __restrict__ Cv,
        int Kn, int lda, int ldb, int ldc,
        long long sA, long long sB, long long sC,
        const float* __restrict__ bias, int sBias, float alpha,
        float* __restrict__ colsum, int sCol)
{
    extern __shared__ char smem[];
    const uint32_t smem_b = smem_u32(smem);
    const int h = blockIdx.z;
    A += (long long)h * sA;
    B += (long long)h * sB;

    const int t = threadIdx.x;
    const int wid = t >> 5, lane = t & 31;
    const int lr = lane >> 2;    // 0..7
    const int lc = lane & 3;     // 0..3
    const int wm = (wid & 1) * 64;
    const int wn = (wid >> 1) * 32;
    const int row0 = blockIdx.y * BM;
    const int col0 = blockIdx.x * BN;
    const int nKT = Kn / BKH;

    const int fr0 = t >> 2, fo = t & 3;
    const int fr1 = (t + 256) >> 2;
    const uint32_t fd0 = (uint32_t)(fo * 16) ^ ((fr0 & 2) << 4);
    const uint32_t fd1 = (uint32_t)(fo * 16) ^ ((fr1 & 2) << 4);

#define LOAD_TILE(kt, s) do { \
    long long _k0 = (long long)(kt) * BKH; \
    uint32_t _sa = smem_b + (s) * STAGE_BYTES; \
    uint32_t _sb = _sa + TILE_BYTES_H; \
    CP_ASYNC16(_sa + fr0 * 64 + fd0, A + (long long)(row0 + fr0) * lda + _k0 + fo * 8); \
    CP_ASYNC16(_sa + fr1 * 64 + fd1, A + (long long)(row0 + fr1) * lda + _k0 + fo * 8); \
    CP_ASYNC16(_sb + fr0 * 64 + fd0, B + (long long)(col0 + fr0) * ldb + _k0 + fo * 8); \
    CP_ASYNC16(_sb + fr1 * 64 + fd1, B + (long long)(col0 + fr1) * ldb + _k0 + fo * 8); \
} while (0)

    float acc[4][4][4];
#pragma unroll
    for (int i = 0; i < 4; i++)
#pragma unroll
        for (int j = 0; j < 4; j++)
#pragma unroll
            for (int q = 0; q < 4; q++) acc[i][j][q] = 0.0f;

    LOAD_TILE(0, 0); CP_COMMIT();
    LOAD_TILE(1, 1); CP_COMMIT();
    LOAD_TILE(2, 2); CP_COMMIT();

    const uint32_t swz = (uint32_t)((lr & 2) << 4);

    for (int it = 0; it < nKT; it++) {
        CP_WAIT2();
        __syncthreads();
        if (it + 3 < nKT) LOAD_TILE(it + 3, (it + 3) & 3);
        CP_COMMIT();

        const char* As = smem + (it & 3) * STAGE_BYTES;
        const char* Bs = As + TILE_BYTES_H;
#pragma unroll
        for (int ks = 0; ks < 2; ks++) {
            const uint32_t koff = (uint32_t)(lc * 8) + (((uint32_t)ks << 5) ^ swz);
            uint2 al[4], ah[4], b[4];
#pragma unroll
            for (int i = 0; i < 4; i++) {
                const int ra = wm + i * 16 + lr;
                al[i] = *(const uint2*)(As + ra * 64 + koff);
                ah[i] = *(const uint2*)(As + (ra + 8) * 64 + koff);
            }
#pragma unroll
            for (int j = 0; j < 4; j++) {
                const int rb = wn + j * 8 + lr;
                b[j] = *(const uint2*)(Bs + rb * 64 + koff);
            }
#pragma unroll
            for (int i = 0; i < 4; i++)
#pragma unroll
                for (int j = 0; j < 4; j++)
                    MMA_F16(acc[i][j], al[i].x, ah[i].x, al[i].y, ah[i].y, b[j].x, b[j].y);
        }
    }

    // epilogue
    const long long co = (long long)h * sC;
    float*  Cf = (float*)Cv + co;
    __half* Ch = (__half*)Cv + co;
#pragma unroll
    for (int j = 0; j < 4; j++) {
        const int c = col0 + wn + j * 8 + lc * 2;
        float b0 = 0.0f, b1 = 0.0f;
        if (MODE == MODE_BIAS) {
            b0 = bias[(long long)h * sBias + c];
            b1 = bias[(long long)h * sBias + c + 1];
        }
        float s0 = 0.0f, s1 = 0.0f;
#pragma unroll
        for (int i = 0; i < 4; i++) {
            const int r = row0 + wm + i * 16 + lr;
            float d0 = acc[i][j][0], d1 = acc[i][j][1];
            float d2 = acc[i][j][2], d3 = acc[i][j][3];
            if (MODE == MODE_EXP) {
                d0 = __expf(d0 * alpha); d1 = __expf(d1 * alpha);
                d2 = __expf(d2 * alpha); d3 = __expf(d3 * alpha);
                s0 += d0 + d2; s1 += d1 + d3;
            } else if (MODE == MODE_BIAS) {
                d0 += b0; d1 += b1; d2 += b0; d3 += b1;
            }
            if (PR) {
                const int pc = perm16(c);   // c even -> perm16(c+1) == pc+1
                *(__half2*)&Ch[(long long)r * ldc + pc] = __floats2half2_rn(d0, d1);
                *(__half2*)&Ch[(long long)(r + 8) * ldc + pc] = __floats2half2_rn(d2, d3);
            } else {
                *(float2*)&Cf[(long long)r * ldc + c]       = make_float2(d0, d1);
                *(float2*)&Cf[(long long)(r + 8) * ldc + c] = make_float2(d2, d3);
            }
        }
        if (MODE == MODE_EXP) {
#pragma unroll
            for (int msk = 4; msk <= 16; msk <<= 1) {
                s0 += __shfl_xor_sync(0xFFFFFFFFu, s0, msk);
                s1 += __shfl_xor_sync(0xFFFFFFFFu, s1, msk);
            }
            if (lane < 4) {
                atomicAdd(&colsum[(long long)h * sCol + c], s0);
                atomicAdd(&colsum[(long long)h * sCol + c + 1], s1);
            }
        }
    }
}

// ---------------- prep / softmax kernels ----------------

// fp32 -> fp16 RN, within-16 perm, same layout. total % 16 == 0.
__global__ void converth_k(const float* __restrict__ in, __half* __restrict__ out,
                           long long total) {
    const long long ng = total >> 4;
    for (long long g = (long long)blockIdx.x * blockDim.x + threadIdx.x;
         g < ng; g += (long long)gridDim.x * blockDim.x) {
        const float* p = in + (g << 4);
        __half tmp[16];
#pragma unroll
        for (int j = 0; j < 16; j++) tmp[perm16(j)] = __float2half_rn(p[j]);
        *(uint4*)(out + (g << 4))     = *(uint4*)tmp;
        *(uint4*)(out + (g << 4) + 8) = *(uint4*)(tmp + 8);
    }
}

// fp32 [R,C] (+batch strides) -> half [C,R] RN-rounded, out-col perm16'd
__global__ void transposeh_k(const float* __restrict__ in, __half* __restrict__ out,
                             int R, int C, long long sIn, long long sOut) {
    __shared__ float tile[32][33];
    const int h = blockIdx.z;
    in += (long long)h * sIn;
    out += (long long)h * sOut;
    const int c0 = blockIdx.x * 32, r0 = blockIdx.y * 32;
    const int x = threadIdx.x, y = threadIdx.y;
#pragma unroll
    for (int j = 0; j < 32; j += 8)
        tile[y + j][x] = in[(long long)(r0 + y + j) * C + c0 + x];
    __syncthreads();
#pragma unroll
    for (int j = 0; j < 32; j += 8)
        out[(long long)(c0 + y + j) * R + r0 + perm16(x)] =
            __float2half_rn(tile[x][y + j]);
}

__global__ void zero_colsum_k() {
    int i = blockIdx.x * blockDim.x + threadIdx.x;
    if (i < HEADS * MKNOW) g_colsum[i] = 0.0f;
}

// w[h,n,m] /= colsum[h,m] in place (exact fp32 output); also write RN-rounded,
// perm16'd half copy for the attn GEMM's A operand.
__global__ void normalize_k(float* __restrict__ w, __half* __restrict__ wr) {
    const long long total4 = (long long)HEADS * NSENT * MKNOW / 4;
    for (long long i = (long long)blockIdx.x * blockDim.x + threadIdx.x;
         i < total4; i += (long long)gridDim.x * blockDim.x) {
        long long e = i << 2;
        int h = (int)(e >> 24);
        int m = (int)(e & (MKNOW - 1));
        const float* cs = &g_colsum[h * MKNOW + m];
        float4 v = ((float4*)w)[i];
        v.x /= cs[0]; v.y /= cs[1]; v.z /= cs[2]; v.w /= cs[3];
        ((float4*)w)[i] = v;
        long long rowbase = e - m;
        wr[rowbase + perm16(m)]     = __float2half_rn(v.x);
        wr[rowbase + perm16(m + 1)] = __float2half_rn(v.y);
        wr[rowbase + perm16(m + 2)] = __float2half_rn(v.z);
        wr[rowbase + perm16(m + 3)] = __float2half_rn(v.w);
    }
}

// ---------------- launch ----------------
extern "C" void kernel_launch(void* const* d_in, const int* in_sizes, int n_in,
                              void* d_out, int out_size)
{
    const float* sentences = (const float*)d_in[0];
    const float* knowledge = (const float*)d_in[1];
    const float* W_s = (const float*)d_in[2];
    const float* b_s = (const float*)d_in[3];
    const float* W_k = (const float*)d_in[4];
    const float* b_k = (const float*)d_in[5];
    const float* W_f = (const float*)d_in[6];
    const float* b_f = (const float*)d_in[7];

    float* out0 = (float*)d_out;                        // [4096,1024]
    float* wout = out0 + (long long)NSENT * SENTD;      // [8*4096,4096]

    __half* gSentH = nullptr; cudaGetSymbolAddress((void**)&gSentH, g_sentH);
    __half* gKnowH = nullptr; cudaGetSymbolAddress((void**)&gKnowH, g_knowH);
    __half* gWsT = nullptr;   cudaGetSymbolAddress((void**)&gWsT, g_WsTh);
    __half* gWkT = nullptr;   cudaGetSymbolAddress((void**)&gWkT, g_WkTh);
    __half* gSh = nullptr;    cudaGetSymbolAddress((void**)&gSh, g_Sh);
    __half* gKph = nullptr;   cudaGetSymbolAddress((void**)&gKph, g_Kph);
    __half* gKnT = nullptr;   cudaGetSymbolAddress((void**)&gKnT, g_knowTh);
    __half* gWfT = nullptr;   cudaGetSymbolAddress((void**)&gWfT, g_WfTh);
    __half* gCc = nullptr;    cudaGetSymbolAddress((void**)&gCc, g_concath);
    __half* gWr = nullptr;    cudaGetSymbolAddress((void**)&gWr, g_wrndh);
    float* gCs = nullptr;     cudaGetSymbolAddress((void**)&gCs, g_colsum);

    cudaFuncSetAttribute(hgemm_k<MODE_BIAS, 1>,  cudaFuncAttributeMaxDynamicSharedMemorySize, SMEM_BYTES);
    cudaFuncSetAttribute(hgemm_k<MODE_EXP, 0>,   cudaFuncAttributeMaxDynamicSharedMemorySize, SMEM_BYTES);
    cudaFuncSetAttribute(hgemm_k<MODE_PLAIN, 1>, cudaFuncAttributeMaxDynamicSharedMemorySize, SMEM_BYTES);
    cudaFuncSetAttribute(hgemm_k<MODE_BIAS, 0>,  cudaFuncAttributeMaxDynamicSharedMemorySize, SMEM_BYTES);

    const float inv_sqrt_hd = 0.08838834764831845f;

    // --- prep: fp16 converts + transposes (all K-perm16'd) ---
    converth_k<<<1024, 256>>>(sentences, gSentH, (long long)NSENT * SENTD);
    converth_k<<<1024, 256>>>(knowledge, gKnowH, (long long)MKNOW * SENTD);
    transposeh_k<<<dim3(HD / 32, SENTD / 32, HEADS), dim3(32, 8)>>>(
        W_s, gWsT, SENTD, HD, (long long)SENTD * HD, (long long)HD * SENTD);
    transposeh_k<<<dim3(HD / 32, SENTD / 32, HEADS), dim3(32, 8)>>>(
        W_k, gWkT, SENTD, HD, (long long)SENTD * HD, (long long)HD * SENTD);
    transposeh_k<<<dim3(SENTD / 32, MKNOW / 32, 1), dim3(32, 8)>>>(
        knowledge, gKnT, MKNOW, SENTD, 0LL, 0LL);
    transposeh_k<<<dim3(SENTD / 32, (HEADS * SENTD) / 32, 1), dim3(32, 8)>>>(
        W_f, gWfT, HEADS * SENTD, SENTD, 0LL, 0LL);
    zero_colsum_k<<<(HEADS * MKNOW + 255) / 256, 256>>>();

    // --- projections (plain fp16, K=1024) -> fp16 perm16 S / Kp ---
    hgemm_k<MODE_BIAS, 1><<<dim3(1, NSENT / BM, HEADS), 256, SMEM_BYTES>>>(
        gSentH, gWsT, gSh, SENTD, SENTD, SENTD, HD,
        0LL, (long long)HD * SENTD, (long long)NSENT * HD, b_s, HD, 0.0f, nullptr, 0);
    hgemm_k<MODE_BIAS, 1><<<dim3(1, MKNOW / BM, HEADS), 256, SMEM_BYTES>>>(
        gKnowH, gWkT, gKph, SENTD, SENTD, SENTD, HD,
        0LL, (long long)HD * SENTD, (long long)MKNOW * HD, b_k, HD, 0.0f, nullptr, 0);

    // --- scores (plain fp16, K=128) -> exp -> fp32 weights output; fused colsum ---
    hgemm_k<MODE_EXP, 0><<<dim3(MKNOW / BN, NSENT / BM, HEADS), 256, SMEM_BYTES>>>(
        gSh, gKph, wout, HD, HD, HD, MKNOW,
        (long long)NSENT * HD, (long long)MKNOW * HD, (long long)NSENT * MKNOW,
        nullptr, 0, inv_sqrt_hd, gCs, MKNOW);

    // --- softmax normalize (exact fp32) + rounded/perm16'd half copy ---
    normalize_k<<<4096, 256>>>(wout, gWr);

    // --- attn: wrnd[h] @ knowT^T -> concat half (perm16'd cols for final GEMM) ---
    hgemm_k<MODE_PLAIN, 1><<<dim3(SENTD / BN, NSENT / BM, HEADS), 256, SMEM_BYTES>>>(
        gWr, gKnT, gCc, MKNOW, MKNOW, MKNOW, HEADS * SENTD,
        (long long)NSENT * MKNOW, 0LL, (long long)SENTD, nullptr, 0, 0.0f, nullptr, 0);

    // --- final: concat @ W_f + b_f (fp16, K=8192) -> fp32 out ---
    hgemm_k<MODE_BIAS, 0><<<dim3(SENTD / BN, NSENT / BM, 1), 256, SMEM_BYTES>>>(
        gCc, gWfT, out0, HEADS * SENTD, HEADS * SENTD, HEADS * SENTD, SENTD,
        0LL, 0LL, 0LL, b_f, 0, 0.0f, nullptr, 0);
}

// round 10
// speedup vs baseline: 1.3687x; 1.0466x over previous
#include <cuda_runtime.h>
#include <cuda_fp16.h>
#include <cstdint>
#include <math.h>

// ---------------- problem constants ----------------
#define NSENT 4096
#define MKNOW 4096
#define HEADS 8
#define SENTD 1024
#define HD    128

// ---------------- GEMM tile config ----------------
#define BM 128
#define BN 128
#define BKH 64                          // k halves per stage (4 mma k16 steps)
#define TILE_BYTES_H (128 * 128)        // 128 rows x 128B
#define STAGE_BYTES (2 * TILE_BYTES_H)  // A + B = 32 KB
#define STAGES 3
#define SMEM_BYTES (STAGES * STAGE_BYTES)   // 96 KB -> 2 CTAs/SM

// ---------------- scratch (static device arrays) ----------------
__device__ __half g_sentH[(size_t)NSENT*SENTD];
__device__ __half g_knowH[(size_t)MKNOW*SENTD];
__device__ __half g_WsTh[(size_t)HEADS*HD*SENTD];
__device__ __half g_WkTh[(size_t)HEADS*HD*SENTD];
__device__ __half g_Sh [(size_t)HEADS*NSENT*HD];
__device__ __half g_Kph[(size_t)HEADS*MKNOW*HD];
__device__ __half g_knowTh[(size_t)SENTD*MKNOW];
__device__ __half g_WfTh[(size_t)SENTD*HEADS*SENTD];
__device__ __half g_concath[(size_t)NSENT*HEADS*SENTD];
__device__ __half g_wrndh[(size_t)HEADS*NSENT*MKNOW];
__device__ float  g_colsum[HEADS*MKNOW];
__device__ float  g_csinv[HEADS*MKNOW];

// ---------------- helpers ----------------
__device__ __forceinline__ uint32_t smem_u32(const void* p) {
    uint32_t a;
    asm("{ .reg .u64 t; cvta.to.shared.u64 t, %1; cvt.u32.u64 %0, t; }" : "=r"(a) : "l"(p));
    return a;
}
// within-16 K permutation: k = 8b + 2c + r  ->  4c + 2b + r
__device__ __forceinline__ int perm16(int k) {
    return (k & ~15) | (((k >> 1) & 3) << 2) | (((k >> 3) & 1) << 1) | (k & 1);
}

#define CP_ASYNC16(dst, src) \
    asm volatile("cp.async.cg.shared.global [%0], [%1], 16;" :: "r"(dst), "l"(src) : "memory")
#define CP_COMMIT() asm volatile("cp.async.commit_group;" ::: "memory")
#define CP_WAIT1()  asm volatile("cp.async.wait_group 1;" ::: "memory")

#define MMA_F16(d, a0, a1, a2, a3, b0, b1) \
    asm volatile("mma.sync.aligned.m16n8k16.row.col.f32.f16.f16.f32 " \
        "{%0,%1,%2,%3}, {%4,%5,%6,%7}, {%8,%9}, {%0,%1,%2,%3};" \
        : "+f"((d)[0]), "+f"((d)[1]), "+f"((d)[2]), "+f"((d)[3]) \
        : "r"(a0), "r"(a1), "r"(a2), "r"(a3), "r"(b0), "r"(b1))

enum { MODE_PLAIN = 0, MODE_BIAS = 1, MODE_SUM = 3, MODE_EXPW = 6 };

// ---------------- fp16 mma.sync GEMM ----------------
// C[M x N] (+ per-blockIdx.z batch strides) = A[M x K] * B[N x K]^T.
// A, B: __half, stored with the within-16 K permutation (perm16).
// MODE_PLAIN/BIAS + PR=0: C fp32 (+bias). PR=1: C __half, cols perm16'd.
// MODE_SUM:  no C stores; colsum[h][c] += sum over rows of exp(alpha*acc).
// MODE_EXPW: Cf = exp(alpha*acc) * csinv[h][c] (fp32) AND C2 half perm16 copy.
//            (colsum arg carries csinv pointer)
template <int MODE, int PR>
__global__ void __launch_bounds__(256, 2)
hgemm_k(const __half* __restrict__ A, const __half* __restrict__ B, void* __restrict__ Cv,
        __half* __restrict__ C2, long long sC2,
        int Kn, int lda, int ldb, int ldc,
        long long sA, long long sB, long long sC,
        const float* __restrict__ bias, int sBias, float alpha,
        float* __restrict__ colsum, int sCol)
{
    extern __shared__ char smem[];
    const uint32_t smem_b = smem_u32(smem);
    const int h = blockIdx.z;
    A += (long long)h * sA;
    B += (long long)h * sB;

    const int t = threadIdx.x;
    const int wid = t >> 5, lane = t & 31;
    const int lr = lane >> 2;    // 0..7
    const int lc = lane & 3;     // 0..3
    const int wm = (wid & 1) * 64;
    const int wn = (wid >> 1) * 32;
    const int row0 = blockIdx.y * BM;
    const int col0 = blockIdx.x * BN;
    const int nKT = Kn / BKH;

    // fill mapping: per operand 128 rows x 8 chunks(16B); 4 chunks/thread
    // smem slot of chunk o in row r: o ^ ((r&3)<<1)   (conflict-free swizzle)
#define LOAD_TILE(kt, s) do { \
    long long _k0 = (long long)(kt) * BKH; \
    uint32_t _sa = smem_b + (s) * STAGE_BYTES; \
    uint32_t _sb2 = _sa + TILE_BYTES_H; \
    _Pragma("unroll") \
    for (int _q = 0; _q < 4; _q++) { \
        int _ci = t + _q * 256; \
        int _r = _ci >> 3, _o = _ci & 7; \
        uint32_t _d = _r * 128 + (uint32_t)((_o ^ ((_r & 3) << 1)) << 4); \
        CP_ASYNC16(_sa + _d,  A + (long long)(row0 + _r) * lda + _k0 + _o * 8); \
        CP_ASYNC16(_sb2 + _d, B + (long long)(col0 + _r) * ldb + _k0 + _o * 8); \
    } \
} while (0)

    float acc[4][4][4];
#pragma unroll
    for (int i = 0; i < 4; i++)
#pragma unroll
        for (int j = 0; j < 4; j++)
#pragma unroll
            for (int q = 0; q < 4; q++) acc[i][j][q] = 0.0f;

    LOAD_TILE(0, 0); CP_COMMIT();
    LOAD_TILE(1, 1); CP_COMMIT();

    const uint32_t sx = (uint32_t)((lr & 3) << 1);   // row&3 == lr&3 for all fragment rows
    const uint32_t inb = (uint32_t)((lc & 1) * 8);   // byte within 16B chunk
    const uint32_t ch0 = (uint32_t)(lc >> 1);        // chunk within 32B k-group

    int sb = 0;  // = it % 3
    for (int it = 0; it < nKT; it++) {
        CP_WAIT1();
        __syncthreads();
        if (it + 2 < nKT) {
            int sl = sb + 2; if (sl >= STAGES) sl -= STAGES;
            LOAD_TILE(it + 2, sl);
        }
        CP_COMMIT();

        const char* As = smem + sb * STAGE_BYTES;
        const char* Bs = As + TILE_BYTES_H;
#pragma unroll
        for (int ks = 0; ks < 4; ks++) {
            const uint32_t aoff = (((ch0 + 2 * ks) ^ sx) << 4) + inb;
            uint2 al[4], ah[4], b[4];
#pragma unroll
            for (int i = 0; i < 4; i++) {
                const int ra = wm + i * 16 + lr;
                al[i] = *(const uint2*)(As + ra * 128 + aoff);
                ah[i] = *(const uint2*)(As + (ra + 8) * 128 + aoff);
            }
#pragma unroll
            for (int j = 0; j < 4; j++) {
                const int rb = wn + j * 8 + lr;
                b[j] = *(const uint2*)(Bs + rb * 128 + aoff);
            }
#pragma unroll
            for (int i = 0; i < 4; i++)
#pragma unroll
                for (int j = 0; j < 4; j++)
                    MMA_F16(acc[i][j], al[i].x, ah[i].x, al[i].y, ah[i].y, b[j].x, b[j].y);
        }
        sb++; if (sb == STAGES) sb = 0;
    }

    // epilogue
    const long long co = (long long)h * sC;
    float*  Cf = (float*)Cv + co;
    __half* Ch = (__half*)Cv + co;
    __half* Ch2 = C2 + (long long)h * sC2;
#pragma unroll
    for (int j = 0; j < 4; j++) {
        const int c = col0 + wn + j * 8 + lc * 2;
        float b0 = 0.0f, b1 = 0.0f;
        if (MODE == MODE_BIAS) {
            b0 = bias[(long long)h * sBias + c];
            b1 = bias[(long long)h * sBias + c + 1];
        }
        float inv0 = 0.0f, inv1 = 0.0f;
        if (MODE == MODE_EXPW) {
            inv0 = colsum[(long long)h * sCol + c];       // csinv
            inv1 = colsum[(long long)h * sCol + c + 1];
        }
        float s0 = 0.0f, s1 = 0.0f;
#pragma unroll
        for (int i = 0; i < 4; i++) {
            const int r = row0 + wm + i * 16 + lr;
            float d0 = acc[i][j][0], d1 = acc[i][j][1];
            float d2 = acc[i][j][2], d3 = acc[i][j][3];
            if (MODE == MODE_SUM) {
                d0 = __expf(d0 * alpha); d1 = __expf(d1 * alpha);
                d2 = __expf(d2 * alpha); d3 = __expf(d3 * alpha);
                s0 += d0 + d2; s1 += d1 + d3;
            } else if (MODE == MODE_EXPW) {
                d0 = __expf(d0 * alpha) * inv0; d1 = __expf(d1 * alpha) * inv1;
                d2 = __expf(d2 * alpha) * inv0; d3 = __expf(d3 * alpha) * inv1;
                const int pc = perm16(c);
                *(float2*)&Cf[(long long)r * ldc + c]       = make_float2(d0, d1);
                *(float2*)&Cf[(long long)(r + 8) * ldc + c] = make_float2(d2, d3);
                *(__half2*)&Ch2[(long long)r * ldc + pc]       = __floats2half2_rn(d0, d1);
                *(__half2*)&Ch2[(long long)(r + 8) * ldc + pc] = __floats2half2_rn(d2, d3);
            } else if (MODE == MODE_BIAS) {
                d0 += b0; d1 += b1; d2 += b0; d3 += b1;
            }
            if (MODE == MODE_PLAIN || MODE == MODE_BIAS) {
                if (PR) {
                    const int pc = perm16(c);   // c even -> perm16(c+1) == pc+1
                    *(__half2*)&Ch[(long long)r * ldc + pc] = __floats2half2_rn(d0, d1);
                    *(__half2*)&Ch[(long long)(r + 8) * ldc + pc] = __floats2half2_rn(d2, d3);
                } else {
                    *(float2*)&Cf[(long long)r * ldc + c]       = make_float2(d0, d1);
                    *(float2*)&Cf[(long long)(r + 8) * ldc + c] = make_float2(d2, d3);
                }
            }
        }
        if (MODE == MODE_SUM) {
#pragma unroll
            for (int msk = 4; msk <= 16; msk <<= 1) {
                s0 += __shfl_xor_sync(0xFFFFFFFFu, s0, msk);
                s1 += __shfl_xor_sync(0xFFFFFFFFu, s1, msk);
            }
            if (lane < 4) {
                atomicAdd(&colsum[(long long)h * sCol + c], s0);
                atomicAdd(&colsum[(long long)h * sCol + c + 1], s1);
            }
        }
    }
}

// ---------------- prep / softmax kernels ----------------

// fp32 -> fp16 RN, within-16 perm, same layout. total % 16 == 0.
__global__ void converth_k(const float* __restrict__ in, __half* __restrict__ out,
                           long long total) {
    const long long ng = total >> 4;
    for (long long g = (long long)blockIdx.x * blockDim.x + threadIdx.x;
         g < ng; g += (long long)gridDim.x * blockDim.x) {
        const float* p = in + (g << 4);
        __half tmp[16];
#pragma unroll
        for (int j = 0; j < 16; j++) tmp[perm16(j)] = __float2half_rn(p[j]);
        *(uint4*)(out + (g << 4))     = *(uint4*)tmp;
        *(uint4*)(out + (g << 4) + 8) = *(uint4*)(tmp + 8);
    }
}

// fp32 [R,C] (+batch strides) -> half [C,R] RN-rounded, out-col perm16'd
__global__ void transposeh_k(const float* __restrict__ in, __half* __restrict__ out,
                             int R, int C, long long sIn, long long sOut) {
    __shared__ float tile[32][33];
    const int h = blockIdx.z;
    in += (long long)h * sIn;
    out += (long long)h * sOut;
    const int c0 = blockIdx.x * 32, r0 = blockIdx.y * 32;
    const int x = threadIdx.x, y = threadIdx.y;
#pragma unroll
    for (int j = 0; j < 32; j += 8)
        tile[y + j][x] = in[(long long)(r0 + y + j) * C + c0 + x];
    __syncthreads();
#pragma unroll
    for (int j = 0; j < 32; j += 8)
        out[(long long)(c0 + y + j) * R + r0 + perm16(x)] =
            __float2half_rn(tile[x][y + j]);
}

__global__ void zero_colsum_k() {
    int i = blockIdx.x * blockDim.x + threadIdx.x;
    if (i < HEADS * MKNOW) g_colsum[i] = 0.0f;
}

__global__ void csinv_k() {
    int i = blockIdx.x * blockDim.x + threadIdx.x;
    if (i < HEADS * MKNOW) g_csinv[i] = 1.0f / g_colsum[i];
}

// ---------------- launch ----------------
extern "C" void kernel_launch(void* const* d_in, const int* in_sizes, int n_in,
                              void* d_out, int out_size)
{
    const float* sentences = (const float*)d_in[0];
    const float* knowledge = (const float*)d_in[1];
    const float* W_s = (const float*)d_in[2];
    const float* b_s = (const float*)d_in[3];
    const float* W_k = (const float*)d_in[4];
    const float* b_k = (const float*)d_in[5];
    const float* W_f = (const float*)d_in[6];
    const float* b_f = (const float*)d_in[7];

    float* out0 = (float*)d_out;                        // [4096,1024]
    float* wout = out0 + (long long)NSENT * SENTD;      // [8*4096,4096]

    __half* gSentH = nullptr; cudaGetSymbolAddress((void**)&gSentH, g_sentH);
    __half* gKnowH = nullptr; cudaGetSymbolAddress((void**)&gKnowH, g_knowH);
    __half* gWsT = nullptr;   cudaGetSymbolAddress((void**)&gWsT, g_WsTh);
    __half* gWkT = nullptr;   cudaGetSymbolAddress((void**)&gWkT, g_WkTh);
    __half* gSh = nullptr;    cudaGetSymbolAddress((void**)&gSh, g_Sh);
    __half* gKph = nullptr;   cudaGetSymbolAddress((void**)&gKph, g_Kph);
    __half* gKnT = nullptr;   cudaGetSymbolAddress((void**)&gKnT, g_knowTh);
    __half* gWfT = nullptr;   cudaGetSymbolAddress((void**)&gWfT, g_WfTh);
    __half* gCc = nullptr;    cudaGetSymbolAddress((void**)&gCc, g_concath);
    __half* gWr = nullptr;    cudaGetSymbolAddress((void**)&gWr, g_wrndh);
    float* gCs = nullptr;     cudaGetSymbolAddress((void**)&gCs, g_colsum);
    float* gCi = nullptr;     cudaGetSymbolAddress((void**)&gCi, g_csinv);

    cudaFuncSetAttribute(hgemm_k<MODE_BIAS, 1>,  cudaFuncAttributeMaxDynamicSharedMemorySize, SMEM_BYTES);
    cudaFuncSetAttribute(hgemm_k<MODE_SUM, 0>,   cudaFuncAttributeMaxDynamicSharedMemorySize, SMEM_BYTES);
    cudaFuncSetAttribute(hgemm_k<MODE_EXPW, 0>,  cudaFuncAttributeMaxDynamicSharedMemorySize, SMEM_BYTES);
    cudaFuncSetAttribute(hgemm_k<MODE_PLAIN, 1>, cudaFuncAttributeMaxDynamicSharedMemorySize, SMEM_BYTES);
    cudaFuncSetAttribute(hgemm_k<MODE_BIAS, 0>,  cudaFuncAttributeMaxDynamicSharedMemorySize, SMEM_BYTES);

    const float inv_sqrt_hd = 0.08838834764831845f;

    // --- prep: fp16 converts + transposes (all K-perm16'd) ---
    converth_k<<<1024, 256>>>(sentences, gSentH, (long long)NSENT * SENTD);
    converth_k<<<1024, 256>>>(knowledge, gKnowH, (long long)MKNOW * SENTD);
    transposeh_k<<<dim3(HD / 32, SENTD / 32, HEADS), dim3(32, 8)>>>(
        W_s, gWsT, SENTD, HD, (long long)SENTD * HD, (long long)HD * SENTD);
    transposeh_k<<<dim3(HD / 32, SENTD / 32, HEADS), dim3(32, 8)>>>(
        W_k, gWkT, SENTD, HD, (long long)SENTD * HD, (long long)HD * SENTD);
    transposeh_k<<<dim3(SENTD / 32, MKNOW / 32, 1), dim3(32, 8)>>>(
        knowledge, gKnT, MKNOW, SENTD, 0LL, 0LL);
    transposeh_k<<<dim3(SENTD / 32, (HEADS * SENTD) / 32, 1), dim3(32, 8)>>>(
        W_f, gWfT, HEADS * SENTD, SENTD, 0LL, 0LL);
    zero_colsum_k<<<(HEADS * MKNOW + 255) / 256, 256>>>();

    // --- projections (plain fp16, K=1024) -> fp16 perm16 S / Kp ---
    hgemm_k<MODE_BIAS, 1><<<dim3(1, NSENT / BM, HEADS), 256, SMEM_BYTES>>>(
        gSentH, gWsT, gSh, nullptr, 0LL, SENTD, SENTD, SENTD, HD,
        0LL, (long long)HD * SENTD, (long long)NSENT * HD, b_s, HD, 0.0f, nullptr, 0);
    hgemm_k<MODE_BIAS, 1><<<dim3(1, MKNOW / BM, HEADS), 256, SMEM_BYTES>>>(
        gKnowH, gWkT, gKph, nullptr, 0LL, SENTD, SENTD, SENTD, HD,
        0LL, (long long)HD * SENTD, (long long)MKNOW * HD, b_k, HD, 0.0f, nullptr, 0);

    // --- scores pass 1 (K=128): colsum only, no stores ---
    hgemm_k<MODE_SUM, 0><<<dim3(MKNOW / BN, NSENT / BM, HEADS), 256, SMEM_BYTES>>>(
        gSh, gKph, nullptr, nullptr, 0LL, HD, HD, HD, MKNOW,
        (long long)NSENT * HD, (long long)MKNOW * HD, 0LL,
        nullptr, 0, inv_sqrt_hd, gCs, MKNOW);

    // --- reciprocal column sums ---
    csinv_k<<<(HEADS * MKNOW + 255) / 256, 256>>>();

    // --- scores pass 2: recompute, write normalized weights fp32 + fp16 perm copy ---
    hgemm_k<MODE_EXPW, 0><<<dim3(MKNOW / BN, NSENT / BM, HEADS), 256, SMEM_BYTES>>>(
        gSh, gKph, wout, gWr, (long long)NSENT * MKNOW, HD, HD, HD, MKNOW,
        (long long)NSENT * HD, (long long)MKNOW * HD, (long long)NSENT * MKNOW,
        nullptr, 0, inv_sqrt_hd, gCi, MKNOW);

    // --- attn: wrnd[h] @ knowT^T -> concat half (perm16'd cols for final GEMM) ---
    hgemm_k<MODE_PLAIN, 1><<<dim3(SENTD / BN, NSENT / BM, HEADS), 256, SMEM_BYTES>>>(
        gWr, gKnT, gCc, nullptr, 0LL, MKNOW, MKNOW, MKNOW, HEADS * SENTD,
        (long long)NSENT * MKNOW, 0LL, (long long)SENTD, nullptr, 0, 0.0f, nullptr, 0);

    // --- final: concat @ W_f + b_f (fp16, K=8192) -> fp32 out ---
    hgemm_k<MODE_BIAS, 0><<<dim3(SENTD / BN, NSENT / BM, 1), 256, SMEM_BYTES>>>(
        gCc, gWfT, out0, nullptr, 0LL, HEADS * SENTD, HEADS * SENTD, HEADS * SENTD, SENTD,
        0LL, 0LL, 0LL, b_f, 0, 0.0f, nullptr, 0);
}

// round 11
// speedup vs baseline: 1.3706x; 1.0014x over previous
#include <cuda_runtime.h>
#include <cuda_fp16.h>
#include <cstdint>
#include <math.h>

// ---------------- problem constants ----------------
#define NSENT 4096
#define MKNOW 4096
#define HEADS 8
#define SENTD 1024
#define HD    128

// ---------------- GEMM tile config ----------------
#define BM 128
#define BN 128
#define BKH 64                          // k halves per stage (4 mma k16 steps)
#define TILE_BYTES_H (128 * 128)        // 128 rows x 128B
#define STAGE_BYTES (2 * TILE_BYTES_H)  // A + B = 32 KB
#define STAGES 3
#define SMEM_BYTES (STAGES * STAGE_BYTES)   // 96 KB -> 2 CTAs/SM

// ---------------- scratch (static device arrays) ----------------
__device__ __half g_sentH[(size_t)NSENT*SENTD];
__device__ __half g_knowH[(size_t)MKNOW*SENTD];
__device__ __half g_WsTh[(size_t)HEADS*HD*SENTD];
__device__ __half g_WkTh[(size_t)HEADS*HD*SENTD];
__device__ __half g_Sh [(size_t)HEADS*NSENT*HD];
__device__ __half g_Kph[(size_t)HEADS*MKNOW*HD];
__device__ __half g_WfTh[(size_t)SENTD*HEADS*SENTD];
__device__ __half g_PTh[(size_t)HEADS*SENTD*MKNOW];     // PT[h][e][m] = (know @ Wf_h)^T
__device__ __half g_wrndh[(size_t)HEADS*NSENT*MKNOW];
__device__ float  g_colsum[HEADS*MKNOW];
__device__ float  g_csinv[HEADS*MKNOW];

// ---------------- helpers ----------------
__device__ __forceinline__ uint32_t smem_u32(const void* p) {
    uint32_t a;
    asm("{ .reg .u64 t; cvta.to.shared.u64 t, %1; cvt.u32.u64 %0, t; }" : "=r"(a) : "l"(p));
    return a;
}
// within-16 K permutation: k = 8b + 2c + r  ->  4c + 2b + r
__device__ __forceinline__ int perm16(int k) {
    return (k & ~15) | (((k >> 1) & 3) << 2) | (((k >> 3) & 1) << 1) | (k & 1);
}

#define CP_ASYNC16(dst, src) \
    asm volatile("cp.async.cg.shared.global [%0], [%1], 16;" :: "r"(dst), "l"(src) : "memory")
#define CP_COMMIT() asm volatile("cp.async.commit_group;" ::: "memory")
#define CP_WAIT1()  asm volatile("cp.async.wait_group 1;" ::: "memory")

#define MMA_F16(d, a0, a1, a2, a3, b0, b1) \
    asm volatile("mma.sync.aligned.m16n8k16.row.col.f32.f16.f16.f32 " \
        "{%0,%1,%2,%3}, {%4,%5,%6,%7}, {%8,%9}, {%0,%1,%2,%3};" \
        : "+f"((d)[0]), "+f"((d)[1]), "+f"((d)[2]), "+f"((d)[3]) \
        : "r"(a0), "r"(a1), "r"(a2), "r"(a3), "r"(b0), "r"(b1))

enum { MODE_PLAIN = 0, MODE_BIAS = 1, MODE_SUM = 3, MODE_EXPW = 6, MODE_RED = 7 };

// ---------------- fp16 mma.sync GEMM ----------------
// C[M x N] (+ per-blockIdx.z batch strides) = A[M x K] * B[N x K]^T.
// A, B: __half, stored with the within-16 K permutation (perm16).
// MODE_PLAIN/BIAS + PR=0: C fp32 (+bias). PR=1: C __half, cols perm16'd.
// MODE_SUM:  no C stores; colsum[h][c] += sum over rows of exp(alpha*acc).
// MODE_EXPW: Cf = exp(alpha*acc) * csinv[h][c] (fp32, st.cs) + C2 half perm16 copy.
// MODE_RED:  atomicAdd acc into Cf (split-K over blockIdx.z; sC = 0).
template <int MODE, int PR>
__global__ void __launch_bounds__(256, 2)
hgemm_k(const __half* __restrict__ A, const __half* __restrict__ B, void* __restrict__ Cv,
        __half* __restrict__ C2, long long sC2,
        int Kn, int lda, int ldb, int ldc,
        long long sA, long long sB, long long sC,
        const float* __restrict__ bias, int sBias, float alpha,
        float* __restrict__ colsum, int sCol)
{
    extern __shared__ char smem[];
    const uint32_t smem_b = smem_u32(smem);
    const int h = blockIdx.z;
    A += (long long)h * sA;
    B += (long long)h * sB;

    const int t = threadIdx.x;
    const int wid = t >> 5, lane = t & 31;
    const int lr = lane >> 2;    // 0..7
    const int lc = lane & 3;     // 0..3
    const int wm = (wid & 1) * 64;
    const int wn = (wid >> 1) * 32;
    const int row0 = blockIdx.y * BM;
    const int col0 = blockIdx.x * BN;
    const int nKT = Kn / BKH;

    // fill mapping: per operand 128 rows x 8 chunks(16B); 4 chunks/thread
    // smem slot of chunk o in row r: o ^ ((r&3)<<1)   (conflict-free swizzle)
#define LOAD_TILE(kt, s) do { \
    long long _k0 = (long long)(kt) * BKH; \
    uint32_t _sa = smem_b + (s) * STAGE_BYTES; \
    uint32_t _sb2 = _sa + TILE_BYTES_H; \
    _Pragma("unroll") \
    for (int _q = 0; _q < 4; _q++) { \
        int _ci = t + _q * 256; \
        int _r = _ci >> 3, _o = _ci & 7; \
        uint32_t _d = _r * 128 + (uint32_t)((_o ^ ((_r & 3) << 1)) << 4); \
        CP_ASYNC16(_sa + _d,  A + (long long)(row0 + _r) * lda + _k0 + _o * 8); \
        CP_ASYNC16(_sb2 + _d, B + (long long)(col0 + _r) * ldb + _k0 + _o * 8); \
    } \
} while (0)

    float acc[4][4][4];
#pragma unroll
    for (int i = 0; i < 4; i++)
#pragma unroll
        for (int j = 0; j < 4; j++)
#pragma unroll
            for (int q = 0; q < 4; q++) acc[i][j][q] = 0.0f;

    LOAD_TILE(0, 0); CP_COMMIT();
    LOAD_TILE(1, 1); CP_COMMIT();

    const uint32_t sx = (uint32_t)((lr & 3) << 1);   // row&3 == lr&3 for all fragment rows
    const uint32_t inb = (uint32_t)((lc & 1) * 8);   // byte within 16B chunk
    const uint32_t ch0 = (uint32_t)(lc >> 1);        // chunk within 32B k-group

    int sb = 0;  // = it % 3
    for (int it = 0; it < nKT; it++) {
        CP_WAIT1();
        __syncthreads();
        if (it + 2 < nKT) {
            int sl = sb + 2; if (sl >= STAGES) sl -= STAGES;
            LOAD_TILE(it + 2, sl);
        }
        CP_COMMIT();

        const char* As = smem + sb * STAGE_BYTES;
        const char* Bs = As + TILE_BYTES_H;
#pragma unroll
        for (int ks = 0; ks < 4; ks++) {
            const uint32_t aoff = (((ch0 + 2 * ks) ^ sx) << 4) + inb;
            uint2 al[4], ah[4], b[4];
#pragma unroll
            for (int i = 0; i < 4; i++) {
                const int ra = wm + i * 16 + lr;
                al[i] = *(const uint2*)(As + ra * 128 + aoff);
                ah[i] = *(const uint2*)(As + (ra + 8) * 128 + aoff);
            }
#pragma unroll
            for (int j = 0; j < 4; j++) {
                const int rb = wn + j * 8 + lr;
                b[j] = *(const uint2*)(Bs + rb * 128 + aoff);
            }
#pragma unroll
            for (int i = 0; i < 4; i++)
#pragma unroll
                for (int j = 0; j < 4; j++)
                    MMA_F16(acc[i][j], al[i].x, ah[i].x, al[i].y, ah[i].y, b[j].x, b[j].y);
        }
        sb++; if (sb == STAGES) sb = 0;
    }

    // epilogue
    const long long co = (long long)h * sC;
    float*  Cf = (float*)Cv + co;
    __half* Ch = (__half*)Cv + co;
    __half* Ch2 = C2 + (long long)h * sC2;
#pragma unroll
    for (int j = 0; j < 4; j++) {
        const int c = col0 + wn + j * 8 + lc * 2;
        float b0 = 0.0f, b1 = 0.0f;
        if (MODE == MODE_BIAS) {
            b0 = bias[(long long)h * sBias + c];
            b1 = bias[(long long)h * sBias + c + 1];
        }
        float inv0 = 0.0f, inv1 = 0.0f;
        if (MODE == MODE_EXPW) {
            inv0 = colsum[(long long)h * sCol + c];       // csinv
            inv1 = colsum[(long long)h * sCol + c + 1];
        }
        float s0 = 0.0f, s1 = 0.0f;
#pragma unroll
        for (int i = 0; i < 4; i++) {
            const int r = row0 + wm + i * 16 + lr;
            float d0 = acc[i][j][0], d1 = acc[i][j][1];
            float d2 = acc[i][j][2], d3 = acc[i][j][3];
            if (MODE == MODE_SUM) {
                d0 = __expf(d0 * alpha); d1 = __expf(d1 * alpha);
                d2 = __expf(d2 * alpha); d3 = __expf(d3 * alpha);
                s0 += d0 + d2; s1 += d1 + d3;
            } else if (MODE == MODE_EXPW) {
                d0 = __expf(d0 * alpha) * inv0; d1 = __expf(d1 * alpha) * inv1;
                d2 = __expf(d2 * alpha) * inv0; d3 = __expf(d3 * alpha) * inv1;
                const int pc = perm16(c);
                float* p0 = &Cf[(long long)r * ldc + c];
                float* p1 = &Cf[(long long)(r + 8) * ldc + c];
                asm volatile("st.global.cs.v2.f32 [%0], {%1,%2};" :: "l"(p0), "f"(d0), "f"(d1) : "memory");
                asm volatile("st.global.cs.v2.f32 [%0], {%1,%2};" :: "l"(p1), "f"(d2), "f"(d3) : "memory");
                *(__half2*)&Ch2[(long long)r * ldc + pc]       = __floats2half2_rn(d0, d1);
                *(__half2*)&Ch2[(long long)(r + 8) * ldc + pc] = __floats2half2_rn(d2, d3);
            } else if (MODE == MODE_BIAS) {
                d0 += b0; d1 += b1; d2 += b0; d3 += b1;
            }
            if (MODE == MODE_RED) {
                atomicAdd(&Cf[(long long)r * ldc + c],           d0);
                atomicAdd(&Cf[(long long)r * ldc + c + 1],       d1);
                atomicAdd(&Cf[(long long)(r + 8) * ldc + c],     d2);
                atomicAdd(&Cf[(long long)(r + 8) * ldc + c + 1], d3);
            } else if (MODE == MODE_PLAIN || MODE == MODE_BIAS) {
                if (PR) {
                    const int pc = perm16(c);   // c even -> perm16(c+1) == pc+1
                    *(__half2*)&Ch[(long long)r * ldc + pc] = __floats2half2_rn(d0, d1);
                    *(__half2*)&Ch[(long long)(r + 8) * ldc + pc] = __floats2half2_rn(d2, d3);
                } else {
                    *(float2*)&Cf[(long long)r * ldc + c]       = make_float2(d0, d1);
                    *(float2*)&Cf[(long long)(r + 8) * ldc + c] = make_float2(d2, d3);
                }
            }
        }
        if (MODE == MODE_SUM) {
#pragma unroll
            for (int msk = 4; msk <= 16; msk <<= 1) {
                s0 += __shfl_xor_sync(0xFFFFFFFFu, s0, msk);
                s1 += __shfl_xor_sync(0xFFFFFFFFu, s1, msk);
            }
            if (lane < 4) {
                atomicAdd(&colsum[(long long)h * sCol + c], s0);
                atomicAdd(&colsum[(long long)h * sCol + c + 1], s1);
            }
        }
    }
}

// ---------------- prep / softmax kernels ----------------

// fp32 -> fp16 RN, within-16 perm, same layout. total % 16 == 0.
__global__ void converth_k(const float* __restrict__ in, __half* __restrict__ out,
                           long long total) {
    const long long ng = total >> 4;
    for (long long g = (long long)blockIdx.x * blockDim.x + threadIdx.x;
         g < ng; g += (long long)gridDim.x * blockDim.x) {
        const float* p = in + (g << 4);
        __half tmp[16];
#pragma unroll
        for (int j = 0; j < 16; j++) tmp[perm16(j)] = __float2half_rn(p[j]);
        *(uint4*)(out + (g << 4))     = *(uint4*)tmp;
        *(uint4*)(out + (g << 4) + 8) = *(uint4*)(tmp + 8);
    }
}

// fp32 [R,C] (+batch strides) -> half [C,R] RN-rounded, out-col perm16'd
__global__ void transposeh_k(const float* __restrict__ in, __half* __restrict__ out,
                             int R, int C, long long sIn, long long sOut) {
    __shared__ float tile[32][33];
    const int h = blockIdx.z;
    in += (long long)h * sIn;
    out += (long long)h * sOut;
    const int c0 = blockIdx.x * 32, r0 = blockIdx.y * 32;
    const int x = threadIdx.x, y = threadIdx.y;
#pragma unroll
    for (int j = 0; j < 32; j += 8)
        tile[y + j][x] = in[(long long)(r0 + y + j) * C + c0 + x];
    __syncthreads();
#pragma unroll
    for (int j = 0; j < 32; j += 8)
        out[(long long)(c0 + y + j) * R + r0 + perm16(x)] =
            __float2half_rn(tile[x][y + j]);
}

__global__ void zero_colsum_k() {
    int i = blockIdx.x * blockDim.x + threadIdx.x;
    if (i < HEADS * MKNOW) g_colsum[i] = 0.0f;
}

__global__ void csinv_k() {
    int i = blockIdx.x * blockDim.x + threadIdx.x;
    if (i < HEADS * MKNOW) g_csinv[i] = 1.0f / g_colsum[i];
}

// out0[n][e] = b_f[e]  (pre-fill before split-K RED accumulation)
__global__ void initout_k(float* __restrict__ out0, const float* __restrict__ bf) {
    int i = blockIdx.x * blockDim.x + threadIdx.x;     // over 1M float4 groups
    if (i < NSENT * SENTD / 4) {
        int e = (i << 2) & (SENTD - 1);
        ((float4*)out0)[i] = *(const float4*)&bf[e];
    }
}

// ---------------- launch ----------------
extern "C" void kernel_launch(void* const* d_in, const int* in_sizes, int n_in,
                              void* d_out, int out_size)
{
    const float* sentences = (const float*)d_in[0];
    const float* knowledge = (const float*)d_in[1];
    const float* W_s = (const float*)d_in[2];
    const float* b_s = (const float*)d_in[3];
    const float* W_k = (const float*)d_in[4];
    const float* b_k = (const float*)d_in[5];
    const float* W_f = (const float*)d_in[6];
    const float* b_f = (const float*)d_in[7];

    float* out0 = (float*)d_out;                        // [4096,1024]
    float* wout = out0 + (long long)NSENT * SENTD;      // [8*4096,4096]

    __half* gSentH = nullptr; cudaGetSymbolAddress((void**)&gSentH, g_sentH);
    __half* gKnowH = nullptr; cudaGetSymbolAddress((void**)&gKnowH, g_knowH);
    __half* gWsT = nullptr;   cudaGetSymbolAddress((void**)&gWsT, g_WsTh);
    __half* gWkT = nullptr;   cudaGetSymbolAddress((void**)&gWkT, g_WkTh);
    __half* gSh = nullptr;    cudaGetSymbolAddress((void**)&gSh, g_Sh);
    __half* gKph = nullptr;   cudaGetSymbolAddress((void**)&gKph, g_Kph);
    __half* gWfT = nullptr;   cudaGetSymbolAddress((void**)&gWfT, g_WfTh);
    __half* gPT = nullptr;    cudaGetSymbolAddress((void**)&gPT, g_PTh);
    __half* gWr = nullptr;    cudaGetSymbolAddress((void**)&gWr, g_wrndh);
    float* gCs = nullptr;     cudaGetSymbolAddress((void**)&gCs, g_colsum);
    float* gCi = nullptr;     cudaGetSymbolAddress((void**)&gCi, g_csinv);

    cudaFuncSetAttribute(hgemm_k<MODE_BIAS, 1>,  cudaFuncAttributeMaxDynamicSharedMemorySize, SMEM_BYTES);
    cudaFuncSetAttribute(hgemm_k<MODE_PLAIN, 1>, cudaFuncAttributeMaxDynamicSharedMemorySize, SMEM_BYTES);
    cudaFuncSetAttribute(hgemm_k<MODE_SUM, 0>,   cudaFuncAttributeMaxDynamicSharedMemorySize, SMEM_BYTES);
    cudaFuncSetAttribute(hgemm_k<MODE_EXPW, 0>,  cudaFuncAttributeMaxDynamicSharedMemorySize, SMEM_BYTES);
    cudaFuncSetAttribute(hgemm_k<MODE_RED, 0>,   cudaFuncAttributeMaxDynamicSharedMemorySize, SMEM_BYTES);

    const float inv_sqrt_hd = 0.08838834764831845f;

    // --- prep: fp16 converts + transposes (all K-perm16'd) ---
    converth_k<<<1024, 256>>>(sentences, gSentH, (long long)NSENT * SENTD);
    converth_k<<<1024, 256>>>(knowledge, gKnowH, (long long)MKNOW * SENTD);
    transposeh_k<<<dim3(HD / 32, SENTD / 32, HEADS), dim3(32, 8)>>>(
        W_s, gWsT, SENTD, HD, (long long)SENTD * HD, (long long)HD * SENTD);
    transposeh_k<<<dim3(HD / 32, SENTD / 32, HEADS), dim3(32, 8)>>>(
        W_k, gWkT, SENTD, HD, (long long)SENTD * HD, (long long)HD * SENTD);
    transposeh_k<<<dim3(SENTD / 32, (HEADS * SENTD) / 32, 1), dim3(32, 8)>>>(
        W_f, gWfT, HEADS * SENTD, SENTD, 0LL, 0LL);
    zero_colsum_k<<<(HEADS * MKNOW + 255) / 256, 256>>>();
    initout_k<<<(NSENT * SENTD / 4 + 255) / 256, 256>>>(out0, b_f);

    // --- PT[h][e][m] = sum_d Wf[h*1024+d][e] * know[m][d]  (fp16 perm16 cols) ---
    hgemm_k<MODE_PLAIN, 1><<<dim3(MKNOW / BN, SENTD / BM, HEADS), 256, SMEM_BYTES>>>(
        gWfT, gKnowH, gPT, nullptr, 0LL, SENTD, HEADS * SENTD, SENTD, MKNOW,
        (long long)SENTD, 0LL, (long long)SENTD * MKNOW, nullptr, 0, 0.0f, nullptr, 0);

    // --- projections (plain fp16, K=1024) -> fp16 perm16 S / Kp ---
    hgemm_k<MODE_BIAS, 1><<<dim3(1, NSENT / BM, HEADS), 256, SMEM_BYTES>>>(
        gSentH, gWsT, gSh, nullptr, 0LL, SENTD, SENTD, SENTD, HD,
        0LL, (long long)HD * SENTD, (long long)NSENT * HD, b_s, HD, 0.0f, nullptr, 0);
    hgemm_k<MODE_BIAS, 1><<<dim3(1, MKNOW / BM, HEADS), 256, SMEM_BYTES>>>(
        gKnowH, gWkT, gKph, nullptr, 0LL, SENTD, SENTD, SENTD, HD,
        0LL, (long long)HD * SENTD, (long long)MKNOW * HD, b_k, HD, 0.0f, nullptr, 0);

    // --- scores pass 1 (K=128): colsum only, no stores ---
    hgemm_k<MODE_SUM, 0><<<dim3(MKNOW / BN, NSENT / BM, HEADS), 256, SMEM_BYTES>>>(
        gSh, gKph, nullptr, nullptr, 0LL, HD, HD, HD, MKNOW,
        (long long)NSENT * HD, (long long)MKNOW * HD, 0LL,
        nullptr, 0, inv_sqrt_hd, gCs, MKNOW);

    // --- reciprocal column sums ---
    csinv_k<<<(HEADS * MKNOW + 255) / 256, 256>>>();

    // --- scores pass 2: recompute, write normalized weights fp32 (st.cs) + fp16 copy ---
    hgemm_k<MODE_EXPW, 0><<<dim3(MKNOW / BN, NSENT / BM, HEADS), 256, SMEM_BYTES>>>(
        gSh, gKph, wout, gWr, (long long)NSENT * MKNOW, HD, HD, HD, MKNOW,
        (long long)NSENT * HD, (long long)MKNOW * HD, (long long)NSENT * MKNOW,
        nullptr, 0, inv_sqrt_hd, gCi, MKNOW);

    // --- output: out0 += wrnd[h] @ PT[h]^T per head (split-K RED, bias pre-filled) ---
    hgemm_k<MODE_RED, 0><<<dim3(SENTD / BN, NSENT / BM, HEADS), 256, SMEM_BYTES>>>(
        gWr, gPT, out0, nullptr, 0LL, MKNOW, MKNOW, MKNOW, SENTD,
        (long long)NSENT * MKNOW, (long long)SENTD * MKNOW, 0LL,
        nullptr, 0, 0.0f, nullptr, 0);
}